// round 8
// baseline (speedup 1.0000x reference)
#include <cuda_runtime.h>
#include <cuda_bf16.h>
#include <cstdint>

#define DEVINL __device__ __forceinline__

#if defined(__CUDA_ARCH__) && \
    (defined(__CUDA_ARCH_FEAT_SM103_ALL) || defined(__CUDA_ARCH_FEAT_SM100_ALL) || \
     defined(__CUDA_ARCH_FEAT_SM101_ALL) || defined(__CUDA_ARCH_SPECIFIC__) || \
     defined(__CUDA_ARCH_FAMILY_SPECIFIC__))
#define HAS_TCGEN05 1
#else
#define HAS_TCGEN05 0
#endif

namespace s8gemm {

constexpr int MDIM = 4096;
constexpr int KDIM = 4096;
constexpr int NDIM = 8192;

// ---- tcgen05 tiling ----
constexpr int BM = 128;
constexpr int BN = 256;          // two N=128 MMA halves
constexpr int BKE = 64;          // K elems per tile (bf16) = 128 bytes
constexpr int NSTAGE = 3;
constexpr int NKT = KDIM / BKE;  // 64 k-tiles

constexpr int A_TILE = BM * 128;             // 16384 B
constexpr int B_TILE = BN * 128;             // 32768 B
constexpr int STAGE_BYTES = A_TILE + B_TILE; // 49152
constexpr int OFF_BAR   = NSTAGE * STAGE_BYTES;   // 147456
constexpr int OFF_SCALE = OFF_BAR + 64;
constexpr int SMEM_ALLOC = OFF_SCALE + BN * 4 + 1024;

constexpr int TMEM_COLS = 256;
constexpr int MT = MDIM / BM;    // 32
constexpr int NTL = NDIM / BN;   // 32
constexpr int CTAS = MT * NTL;   // 1024
constexpr int THREADS = 512;

// kind::f16 idesc: F32 acc (1<<4), A=BF16 (1<<7), B=BF16 (1<<10),
// N/8<<17, M/16<<24. Both operands K-major -> D = A @ Bt^T = A @ B.
constexpr uint32_t IDESC =
      (1u << 4) | (1u << 7) | (1u << 10)
    | ((128u / 8u) << 17) | ((128u / 16u) << 24);

// K-major SW128 SMEM descriptor (Blackwell version=1): LBO=1, SBO=64.
constexpr uint64_t DESC_BASE_K =
      (uint64_t(2) << 61) | (uint64_t(1) << 46) | (uint64_t(64) << 32) | (uint64_t(1) << 16);

// Scratch. tcgen05 build: pre-swizzled SMEM tile images
//   A block (mt*NKT+kt) = 16KB, B block (nt*NKT+kt) = 32KB.
// Fallback build: linear bf16 A[M][K] / Bt[N][K].
__device__ __align__(1024) uint8_t g_Aimg[(size_t)MT * NKT * A_TILE];    // 32 MB
__device__ __align__(1024) uint8_t g_Bimg[(size_t)NTL * NKT * B_TILE];   // 64 MB

__device__ int g_dtA;   // 0=int8, 1=int32, 2=fp32
__device__ int g_dtB;

DEVINL uint32_t smem_u32(const void* p) {
    uint32_t a;
    asm("{ .reg .u64 t; cvta.to.shared.u64 t, %1; cvt.u32.u64 %0, t; }" : "=r"(a) : "l"(p));
    return a;
}
DEVINL uint32_t sw128(uint32_t off) { return off ^ ((off >> 3) & 0x70u); }

// ---------------------------------------------------------------------------
// Dtype detection — parallel (2 warps, ballots): ~2us instead of ~25us serial.
// ---------------------------------------------------------------------------
__global__ void detect_kernel(const void* a, const void* b) {
    const int t = threadIdx.x;          // 64 threads
    const void* p = (t < 32) ? a : b;
    const int lane = t & 31;
    const int32_t* w = (const int32_t*)p;
    const float*   f = (const float*)p;
    bool i32ok = true, f32ok = true;
    #pragma unroll
    for (int j = 0; j < 2; ++j) {
        const int idx = lane * 2 + j;
        const int32_t v = w[idx];
        i32ok &= (v >= -128 && v <= 127);
        const float x = f[idx];
        f32ok &= (x >= -128.0f && x <= 128.0f && x == truncf(x));
    }
    const uint32_t bi = __ballot_sync(0xFFFFFFFFu, i32ok);
    const uint32_t bf = __ballot_sync(0xFFFFFFFFu, f32ok);
    if (lane == 0) {
        const int dt = (bi == 0xFFFFFFFFu) ? 1 : ((bf == 0xFFFFFFFFu) ? 2 : 0);
        if (t < 32) g_dtA = dt; else g_dtB = dt;
    }
}

// ---------------------------------------------------------------------------
// Pre-pass 1: A -> bf16. tcgen05 build: swizzled tile image. Else: linear.
// ---------------------------------------------------------------------------
__global__ void __launch_bounds__(256) conv_a_kernel(const void* __restrict__ A) {
    const size_t base = ((size_t)blockIdx.x * 256 + threadIdx.x) * 16;
    const int dt = g_dtA;
    __nv_bfloat16 o[16];
    if (dt == 1) {
        const int32_t* p = (const int32_t*)A + base;
        #pragma unroll
        for (int j = 0; j < 16; ++j) o[j] = __float2bfloat16_rn((float)p[j]);
    } else if (dt == 2) {
        const float* p = (const float*)A + base;
        #pragma unroll
        for (int j = 0; j < 16; ++j) o[j] = __float2bfloat16_rn(p[j]);
    } else {
        uint4 v = *reinterpret_cast<const uint4*>((const int8_t*)A + base);
        const int8_t* b = reinterpret_cast<const int8_t*>(&v);
        #pragma unroll
        for (int j = 0; j < 16; ++j) o[j] = __float2bfloat16_rn((float)(int)b[j]);
    }
#if HAS_TCGEN05
    const uint32_t m  = (uint32_t)(base >> 12);
    const uint32_t k  = (uint32_t)(base & 4095);
    const uint32_t mt = m >> 7, r = m & 127;
    const uint32_t kt = k >> 6, kl = k & 63;
    uint8_t* blk = g_Aimg + (size_t)(mt * NKT + kt) * A_TILE;
    *reinterpret_cast<uint4*>(blk + sw128(r * 128 + kl * 2))      = *reinterpret_cast<uint4*>(&o[0]);
    *reinterpret_cast<uint4*>(blk + sw128(r * 128 + kl * 2 + 16)) = *reinterpret_cast<uint4*>(&o[8]);
#else
    __nv_bfloat16* dst = reinterpret_cast<__nv_bfloat16*>(g_Aimg) + base;
    *reinterpret_cast<uint4*>(dst)     = *reinterpret_cast<uint4*>(&o[0]);
    *reinterpret_cast<uint4*>(dst + 8) = *reinterpret_cast<uint4*>(&o[8]);
#endif
}

// ---------------------------------------------------------------------------
// Pre-pass 2: B [K][N] -> Bt bf16 [N][K] (64x64 smem transpose, vectorized).
// ---------------------------------------------------------------------------
__global__ void __launch_bounds__(256) conv_b_kernel(const void* __restrict__ B) {
    __shared__ __nv_bfloat16 t[64][72];   // 144B rows: 16B-aligned vec stores
    const int n0 = blockIdx.x * 64, k0 = blockIdx.y * 64;
    const int r  = threadIdx.x >> 2;
    const int c  = (threadIdx.x & 3) * 16;
    const int dt = g_dtB;

    const size_t src_off = (size_t)(k0 + r) * NDIM + n0 + c;
    __nv_bfloat16 o[16];
    if (dt == 1) {
        const int32_t* p = (const int32_t*)B + src_off;
        #pragma unroll
        for (int j = 0; j < 16; ++j) o[j] = __float2bfloat16_rn((float)p[j]);
    } else if (dt == 2) {
        const float* p = (const float*)B + src_off;
        #pragma unroll
        for (int j = 0; j < 16; ++j) o[j] = __float2bfloat16_rn(p[j]);
    } else {
        uint4 v = *reinterpret_cast<const uint4*>((const int8_t*)B + src_off);
        const int8_t* b = reinterpret_cast<const int8_t*>(&v);
        #pragma unroll
        for (int j = 0; j < 16; ++j) o[j] = __float2bfloat16_rn((float)(int)b[j]);
    }
    *reinterpret_cast<uint4*>(&t[r][c])     = *reinterpret_cast<uint4*>(&o[0]);
    *reinterpret_cast<uint4*>(&t[r][c + 8]) = *reinterpret_cast<uint4*>(&o[8]);
    __syncthreads();

    __nv_bfloat16 q[16];
    #pragma unroll
    for (int j = 0; j < 16; ++j) q[j] = t[c + j][r];     // Bt[n0+r][k0+c+j]

#if HAS_TCGEN05
    const uint32_t ng = n0 + r;
    const uint32_t nt = ng >> 8, nl = ng & 255;
    const uint32_t kt = (uint32_t)k0 >> 6;
    uint8_t* blk = g_Bimg + (size_t)(nt * NKT + kt) * B_TILE;
    *reinterpret_cast<uint4*>(blk + sw128(nl * 128 + c * 2))      = *reinterpret_cast<uint4*>(&q[0]);
    *reinterpret_cast<uint4*>(blk + sw128(nl * 128 + c * 2 + 16)) = *reinterpret_cast<uint4*>(&q[8]);
#else
    __nv_bfloat16* dst = reinterpret_cast<__nv_bfloat16*>(g_Bimg) +
                         (size_t)(n0 + r) * KDIM + k0 + c;
    *reinterpret_cast<uint4*>(dst)     = *reinterpret_cast<uint4*>(&q[0]);
    *reinterpret_cast<uint4*>(dst + 8) = *reinterpret_cast<uint4*>(&q[8]);
#endif
}

#if HAS_TCGEN05
DEVINL void mbar_init(uint32_t bar, uint32_t cnt) {
    asm volatile("mbarrier.init.shared.b64 [%0], %1;" :: "r"(bar), "r"(cnt) : "memory");
}
DEVINL void mbar_wait(uint32_t bar, uint32_t parity) {
    asm volatile(
        "{\n\t"
        ".reg .pred P;\n\t"
        "WAIT_%=:\n\t"
        "mbarrier.try_wait.parity.acquire.cta.shared::cta.b64 P, [%0], %1, 0x989680;\n\t"
        "@P bra.uni DONE_%=;\n\t"
        "bra.uni WAIT_%=;\n\t"
        "DONE_%=:\n\t"
        "}" :: "r"(bar), "r"(parity) : "memory");
}
DEVINL void mbar_expect_tx(uint32_t bar, uint32_t bytes) {
    asm volatile("mbarrier.arrive.expect_tx.shared.b64 _, [%0], %1;"
                 :: "r"(bar), "r"(bytes) : "memory");
}
DEVINL void bulk_g2s(uint32_t dst, const void* src, uint32_t bytes, uint32_t bar) {
    asm volatile(
        "cp.async.bulk.shared::cluster.global.mbarrier::complete_tx::bytes [%0], [%1], %2, [%3];"
        :: "r"(dst), "l"(src), "r"(bytes), "r"(bar) : "memory");
}
DEVINL void bulk_g2s_mc(uint32_t dst, const void* src, uint32_t bytes, uint32_t bar, uint16_t mask) {
    asm volatile(
        "cp.async.bulk.shared::cluster.global.mbarrier::complete_tx::bytes.multicast::cluster "
        "[%0], [%1], %2, [%3], %4;"
        :: "r"(dst), "l"(src), "r"(bytes), "r"(bar), "h"(mask) : "memory");
}
DEVINL void mma_bf16(uint32_t d, uint64_t ad, uint64_t bd, uint32_t idesc, uint32_t acc) {
    asm volatile(
        "{\n\t.reg .pred p;\n\t"
        "setp.ne.u32 p, %5, 0;\n\t"
        "tcgen05.mma.cta_group::1.kind::f16 [%0], %1, %2, %3, {%4, %4, %4, %4}, p;\n\t}"
        :: "r"(d), "l"(ad), "l"(bd), "r"(idesc), "r"(0u), "r"(acc) : "memory");
}
DEVINL void tc_commit(uint32_t bar) {
    asm volatile("tcgen05.commit.cta_group::1.mbarrier::arrive::one.shared::cluster.b64 [%0];"
                 :: "r"(bar) : "memory");
}
DEVINL void tc_commit_mc(uint32_t bar, uint16_t mask) {
    asm volatile(
        "tcgen05.commit.cta_group::1.mbarrier::arrive::one.shared::cluster.multicast::cluster.b64 [%0], %1;"
        :: "r"(bar), "h"(mask) : "memory");
}
DEVINL void tc_fence_after() { asm volatile("tcgen05.fence::after_thread_sync;" ::: "memory"); }
DEVINL void tc_wait_ld() { asm volatile("tcgen05.wait::ld.sync.aligned;" ::: "memory"); }
DEVINL uint32_t ctarank() {
    uint32_t r; asm("mov.u32 %0, %%cluster_ctarank;" : "=r"(r)); return r;
}
DEVINL void cluster_sync() {
    asm volatile("barrier.cluster.arrive.aligned;" ::: "memory");
    asm volatile("barrier.cluster.wait.aligned;" ::: "memory");
}

#define TC_LD_X32(r, addr)                                                     \
    asm volatile(                                                              \
        "tcgen05.ld.sync.aligned.32x32b.x32.b32 "                              \
        "{%0, %1, %2, %3, %4, %5, %6, %7, "                                    \
        " %8, %9, %10, %11, %12, %13, %14, %15, "                              \
        " %16, %17, %18, %19, %20, %21, %22, %23, "                            \
        " %24, %25, %26, %27, %28, %29, %30, %31}, [%32];"                     \
        : "=r"((r)[0]),  "=r"((r)[1]),  "=r"((r)[2]),  "=r"((r)[3]),           \
          "=r"((r)[4]),  "=r"((r)[5]),  "=r"((r)[6]),  "=r"((r)[7]),           \
          "=r"((r)[8]),  "=r"((r)[9]),  "=r"((r)[10]), "=r"((r)[11]),          \
          "=r"((r)[12]), "=r"((r)[13]), "=r"((r)[14]), "=r"((r)[15]),          \
          "=r"((r)[16]), "=r"((r)[17]), "=r"((r)[18]), "=r"((r)[19]),          \
          "=r"((r)[20]), "=r"((r)[21]), "=r"((r)[22]), "=r"((r)[23]),          \
          "=r"((r)[24]), "=r"((r)[25]), "=r"((r)[26]), "=r"((r)[27]),          \
          "=r"((r)[28]), "=r"((r)[29]), "=r"((r)[30]), "=r"((r)[31])           \
        : "r"(addr))
#else
DEVINL void cp_async16(uint32_t dst, const void* src) {
    asm volatile("cp.async.cg.shared.global [%0], [%1], 16;" :: "r"(dst), "l"(src) : "memory");
}
DEVINL void cp_commit() { asm volatile("cp.async.commit_group;" ::: "memory"); }
template <int N> DEVINL void cp_wait() {
    asm volatile("cp.async.wait_group %0;" :: "n"(N) : "memory");
}
DEVINL void ldsm_x4(uint32_t (&r)[4], uint32_t addr) {
    asm volatile("ldmatrix.sync.aligned.m8n8.x4.shared.b16 {%0,%1,%2,%3}, [%4];"
                 : "=r"(r[0]), "=r"(r[1]), "=r"(r[2]), "=r"(r[3]) : "r"(addr));
}
DEVINL void mma16816(float (&d)[4], const uint32_t (&a)[4], uint32_t b0, uint32_t b1) {
    asm volatile(
        "mma.sync.aligned.m16n8k16.row.col.f32.bf16.bf16.f32 "
        "{%0,%1,%2,%3}, {%4,%5,%6,%7}, {%8,%9}, {%0,%1,%2,%3};"
        : "+f"(d[0]), "+f"(d[1]), "+f"(d[2]), "+f"(d[3])
        : "r"(a[0]), "r"(a[1]), "r"(a[2]), "r"(a[3]), "r"(b0), "r"(b1));
}
#endif

__global__ void __launch_bounds__(THREADS, 1) __cluster_dims__(2, 1, 1)
gemm_kernel(const float* __restrict__ scale, float* __restrict__ out)
{
    extern __shared__ char smem_raw[];

#if HAS_TCGEN05
    // =========================================================================
    // tcgen05 pipeline with cluster-2 B-multicast. CTA pair = (mt even/odd,
    // same nt): rank 0 multicasts the shared B tile to both CTAs' SMEM.
    // =========================================================================
    const uint32_t sb_raw = smem_u32(smem_raw);
    const uint32_t sb = (sb_raw + 1023u) & ~1023u;
    char* smem = smem_raw + (sb - sb_raw);

    const int tid = threadIdx.x;
    const int wid = tid >> 5;
    const uint32_t rank = ctarank();

    const int mt = blockIdx.x & 31;   // m-fastest raster; pairs share nt
    const int nt = blockIdx.x >> 5;
    const int m0 = mt * BM;
    const int n0 = nt * BN;

    const uint32_t bar_full0  = sb + OFF_BAR;        // 3 x 8B, count 1 (+tx)
    const uint32_t bar_empty0 = sb + OFF_BAR + 24;   // 3 x 8B, count 2
    const uint32_t bar_done   = sb + OFF_BAR + 48;
    const uint32_t tmem_ptr   = sb + OFF_BAR + 56;
    float* s_scale = reinterpret_cast<float*>(smem + OFF_SCALE);

    if (tid == 0) {
        #pragma unroll
        for (int s = 0; s < NSTAGE; ++s) {
            mbar_init(bar_full0 + s * 8, 1);    // expect_tx arrive
            mbar_init(bar_empty0 + s * 8, 2);   // both consumers' mc-commits
        }
        mbar_init(bar_done, 1);
    }
    if (wid == 0) {
        asm volatile("tcgen05.alloc.cta_group::1.sync.aligned.shared::cta.b32 [%0], %1;"
                     :: "r"(tmem_ptr), "r"(TMEM_COLS) : "memory");
    }
    if (tid < 256) s_scale[tid] = scale[n0 + tid];
    __syncthreads();
    cluster_sync();   // peer mbarriers must be live before any multicast

    uint32_t tmem;
    asm volatile("ld.shared.b32 %0, [%1];" : "=r"(tmem) : "r"(tmem_ptr));

    if (tid == 0) {
        // -------- consumer: wait full, 8 MMAs, multicast-commit empty --------
        int s = 0, ph = 0;
        for (int kt = 0; kt < NKT; ++kt) {
            mbar_wait(bar_full0 + s * 8, ph);
            const uint32_t stg = sb + (uint32_t)s * STAGE_BYTES;
            const uint64_t adesc = DESC_BASE_K | ((stg >> 4) & 0x3FFFu);
            #pragma unroll
            for (int h = 0; h < 2; ++h) {
                const uint64_t bdesc = DESC_BASE_K |
                    (((stg + A_TILE + (uint32_t)h * 16384u) >> 4) & 0x3FFFu);
                #pragma unroll
                for (int q = 0; q < 4; ++q) {
                    mma_bf16(tmem + h * 128,
                             adesc + (uint64_t)(q * 2),
                             bdesc + (uint64_t)(q * 2),
                             IDESC,
                             (kt > 0 || q > 0) ? 1u : 0u);
                }
            }
            tc_commit_mc(bar_empty0 + s * 8, (uint16_t)0x3);  // both CTAs
            if (++s == NSTAGE) { s = 0; ph ^= 1; }
        }
        tc_commit(bar_done);
    } else if (tid == 32) {
        // -------- producer: A local bulk; B multicast from rank 0 only ------
        const uint8_t* gA = g_Aimg + (size_t)(mt * NKT) * A_TILE;
        const uint8_t* gB = g_Bimg + (size_t)(nt * NKT) * B_TILE;
        int s = 0, ph = 1;
        for (int kt = 0; kt < NKT; ++kt) {
            mbar_wait(bar_empty0 + s * 8, ph);   // both consumers freed stage
            const uint32_t stg  = sb + (uint32_t)s * STAGE_BYTES;
            const uint32_t barf = bar_full0 + s * 8;
            mbar_expect_tx(barf, (uint32_t)STAGE_BYTES);
            bulk_g2s(stg, gA + (size_t)kt * A_TILE, (uint32_t)A_TILE, barf);
            if (rank == 0) {
                bulk_g2s_mc(stg + A_TILE, gB + (size_t)kt * B_TILE,
                            (uint32_t)B_TILE, barf, (uint16_t)0x3);
            }
            if (++s == NSTAGE) { s = 0; ph ^= 1; }
        }
    }

    // -------- epilogue: 16 warps; wg g owns 64 cols, subpartition wid%4 ------
    mbar_wait(bar_done, 0);
    tc_fence_after();

    const int lane = tid & 31;
    const int g    = wid >> 2;
    const int sp   = wid & 3;
    const int mrow = m0 + sp * 32 + lane;
    float* orow = out + (size_t)mrow * NDIM + n0 + g * 64;

    #pragma unroll
    for (int half = 0; half < 2; ++half) {
        uint32_t r[32];
        TC_LD_X32(r, tmem + g * 64 + half * 32);
        tc_wait_ld();
        const float* sc = s_scale + g * 64 + half * 32;
        #pragma unroll
        for (int i = 0; i < 32; i += 4) {
            float4 v;
            v.x = __uint_as_float(r[i + 0]) * sc[i + 0];
            v.y = __uint_as_float(r[i + 1]) * sc[i + 1];
            v.z = __uint_as_float(r[i + 2]) * sc[i + 2];
            v.w = __uint_as_float(r[i + 3]) * sc[i + 3];
            *reinterpret_cast<float4*>(orow + half * 32 + i) = v;
        }
    }

    __syncthreads();
    if (wid == 0) {
        asm volatile("tcgen05.dealloc.cta_group::1.sync.aligned.b32 %0, %1;"
                     :: "r"(tmem), "r"(TMEM_COLS));
    }
    cluster_sync();   // no CTA exits while peer commits/multicasts may target it

#else
    // =========================================================================
    // Fallback (compute_103 phase): proven mma.sync engine on linear scratch.
    // =========================================================================
    constexpr int KC = 32;
    constexpr int NKT2 = KDIM / KC;
    constexpr int RSB = 80;
    constexpr int SA_BYTES = BM * RSB;
    constexpr int SB_BYTES = BN * RSB;
    constexpr int STAGE = SA_BYTES + SB_BYTES;

    const uint32_t sb = smem_u32(smem_raw);
    const int tid  = threadIdx.x;
    const int wid  = tid >> 5;
    const int lane = tid & 31;

    const int mt = blockIdx.x & 31;
    const int nt = blockIdx.x >> 5;
    const int m0 = mt * BM;
    const int n0 = nt * BN;

    const int wm = (wid >> 2) * 32;
    const int wn = (wid & 3) * 64;

    const __nv_bfloat16* gA = reinterpret_cast<const __nv_bfloat16*>(g_Aimg) + (size_t)m0 * KDIM;
    const __nv_bfloat16* gB = reinterpret_cast<const __nv_bfloat16*>(g_Bimg) + (size_t)n0 * KDIM;

    auto fill = [&](int buf, int kt) {
        const uint32_t base = sb + buf * STAGE;
        #pragma unroll
        for (int j = 0; j < 3; ++j) {
            const int q = tid + j * THREADS;
            if (q < 512) {
                const int r = q >> 2, c = q & 3;
                cp_async16(base + r * RSB + c * 16, gA + (size_t)r * KDIM + kt * KC + c * 8);
            } else {
                const int qb = q - 512;
                const int r = qb >> 2, c = qb & 3;
                cp_async16(base + SA_BYTES + r * RSB + c * 16,
                           gB + (size_t)r * KDIM + kt * KC + c * 8);
            }
        }
        cp_commit();
    };

    float acc[2][8][4];
    #pragma unroll
    for (int mi = 0; mi < 2; ++mi)
        #pragma unroll
        for (int nf = 0; nf < 8; ++nf)
            #pragma unroll
            for (int k = 0; k < 4; ++k) acc[mi][nf][k] = 0.0f;

    const int lr = lane & 15;
    const int lh = (lane >> 4) * 16;

    fill(0, 0);

    for (int kt = 0; kt < NKT2; ++kt) {
        if (kt + 1 < NKT2) fill((kt + 1) & 1, kt + 1);
        if (kt + 1 < NKT2) cp_wait<1>(); else cp_wait<0>();
        __syncthreads();

        const uint32_t aB = sb + (kt & 1) * STAGE;
        const uint32_t bB = aB + SA_BYTES;

        #pragma unroll
        for (int s = 0; s < 2; ++s) {
            const int kb = s * 32;
            uint32_t av[2][4];
            #pragma unroll
            for (int mi = 0; mi < 2; ++mi)
                ldsm_x4(av[mi], aB + (wm + mi * 16 + lr) * RSB + kb + lh);
            uint32_t bv[4][4];
            #pragma unroll
            for (int nb = 0; nb < 4; ++nb)
                ldsm_x4(bv[nb], bB + (wn + nb * 16 + lr) * RSB + kb + lh);
            #pragma unroll
            for (int mi = 0; mi < 2; ++mi) {
                #pragma unroll
                for (int nb = 0; nb < 4; ++nb) {
                    mma16816(acc[mi][nb * 2 + 0], av[mi], bv[nb][0], bv[nb][2]);
                    mma16816(acc[mi][nb * 2 + 1], av[mi], bv[nb][1], bv[nb][3]);
                }
            }
        }
        __syncthreads();
    }

    const int g  = lane >> 2;
    const int t4 = lane & 3;
    #pragma unroll
    for (int mi = 0; mi < 2; ++mi) {
        const int mrow = m0 + wm + mi * 16 + g;
        #pragma unroll
        for (int nf = 0; nf < 8; ++nf) {
            const int ncol = n0 + wn + nf * 8 + t4 * 2;
            const float s0 = __ldg(&scale[ncol]);
            const float s1 = __ldg(&scale[ncol + 1]);
            float2 v0 = make_float2(acc[mi][nf][0] * s0, acc[mi][nf][1] * s1);
            float2 v1 = make_float2(acc[mi][nf][2] * s0, acc[mi][nf][3] * s1);
            *reinterpret_cast<float2*>(out + (size_t)mrow * NDIM + ncol) = v0;
            *reinterpret_cast<float2*>(out + (size_t)(mrow + 8) * NDIM + ncol) = v1;
        }
    }
#endif
}

} // namespace s8gemm

extern "C" void kernel_launch(void* const* d_in, const int* in_sizes, int n_in,
                              void* d_out, int out_size)
{
    using namespace s8gemm;

    const void* pa = nullptr;
    const void* pb = nullptr;
    const float* ps = nullptr;
    for (int i = 0; i < n_in; ++i) {
        if (in_sizes[i] == MDIM * KDIM)      pa = d_in[i];
        else if (in_sizes[i] == KDIM * NDIM) pb = d_in[i];
        else if (in_sizes[i] == NDIM)        ps = (const float*)d_in[i];
    }
    if (!pa) pa = d_in[0];
    if (!pb) pb = d_in[1];
    if (!ps) ps = (const float*)d_in[2];
    float* out = (float*)d_out;
    (void)out_size;

    detect_kernel<<<1, 64>>>(pa, pb);
    {
        const size_t a_chunks = (size_t)MDIM * KDIM / 16;
        conv_a_kernel<<<(unsigned)(a_chunks / 256), 256>>>(pa);
        dim3 gb(NDIM / 64, KDIM / 64);
        conv_b_kernel<<<gb, 256>>>(pb);
    }

    cudaFuncSetAttribute(gemm_kernel,
                         cudaFuncAttributeMaxDynamicSharedMemorySize, SMEM_ALLOC);
    gemm_kernel<<<CTAS, THREADS, SMEM_ALLOC>>>(ps, out);
}

// round 10
// speedup vs baseline: 1.1357x; 1.1357x over previous
#include <cuda_runtime.h>
#include <cuda_bf16.h>
#include <cstdint>

#define DEVINL __device__ __forceinline__

#if defined(__CUDA_ARCH__) && \
    (defined(__CUDA_ARCH_FEAT_SM103_ALL) || defined(__CUDA_ARCH_FEAT_SM100_ALL) || \
     defined(__CUDA_ARCH_FEAT_SM101_ALL) || defined(__CUDA_ARCH_SPECIFIC__) || \
     defined(__CUDA_ARCH_FAMILY_SPECIFIC__))
#define HAS_TCGEN05 1
#else
#define HAS_TCGEN05 0
#endif

namespace s8gemm {

constexpr int MDIM = 4096;
constexpr int KDIM = 4096;
constexpr int NDIM = 8192;

// ---- tcgen05 tiling: single CTA computes 256(M) x 256(N) ----
constexpr int NSTAGE = 3;
constexpr int NKT = KDIM / 64;    // 64 k-tiles (64 bf16 = 128B rows)

constexpr int A_TILE = 128 * 128;              // 16 KB per 128-row A image block
constexpr int B_TILE = 256 * 128;              // 32 KB per (nt,kt) B image block
constexpr int STAGE_BYTES = 2 * A_TILE + B_TILE;   // 65536
constexpr int OFF_BAR   = NSTAGE * STAGE_BYTES;    // 196608
constexpr int OFF_SCALE = OFF_BAR + 64;
constexpr int SMEM_ALLOC = OFF_SCALE + 256 * 4 + 1024;   // ~198.7 KB

constexpr int TMEM_COLS = 512;    // 2 M-halves x 256 fp32 cols
constexpr int MT = MDIM / 128;    // 32 A image blocks
constexpr int NTL = NDIM / 256;   // 32
constexpr int CTAS = (MDIM / 256) * NTL;   // 512
constexpr int THREADS = 512;

// cg1 kind::f16 idesc: F32 acc, BF16 x BF16, N=128, M=128 (both K-major).
constexpr uint32_t IDESC =
      (1u << 4) | (1u << 7) | (1u << 10)
    | ((128u / 8u) << 17) | ((128u / 16u) << 24);

// K-major SW128 SMEM descriptor (Blackwell version=1): LBO=1, SBO=64.
constexpr uint64_t DESC_BASE_K =
      (uint64_t(2) << 61) | (uint64_t(1) << 46) | (uint64_t(64) << 32) | (uint64_t(1) << 16);

// Scratch images (tcgen05 build):
//   A block (mt128*NKT + kt): 16KB swizzled [128 rows x 128B], mt128 = 0..31.
//   B block (nt*NKT + kt):    32KB swizzled [256 N-rows x 128B].
// Fallback build: linear bf16 A[M][K] / Bt[N][K].
__device__ __align__(1024) uint8_t g_Aimg[(size_t)MT * NKT * A_TILE];    // 32 MB
__device__ __align__(1024) uint8_t g_Bimg[(size_t)NTL * NKT * B_TILE];   // 64 MB

__device__ int g_dtA;   // 0=int8, 1=int32, 2=fp32
__device__ int g_dtB;

DEVINL uint32_t smem_u32(const void* p) {
    uint32_t a;
    asm("{ .reg .u64 t; cvta.to.shared.u64 t, %1; cvt.u32.u64 %0, t; }" : "=r"(a) : "l"(p));
    return a;
}
DEVINL uint32_t sw128(uint32_t off) { return off ^ ((off >> 3) & 0x70u); }

// ---------------------------------------------------------------------------
// Dtype detection (2 warps + ballots).
// ---------------------------------------------------------------------------
__global__ void detect_kernel(const void* a, const void* b) {
    const int t = threadIdx.x;
    const void* p = (t < 32) ? a : b;
    const int lane = t & 31;
    const int32_t* w = (const int32_t*)p;
    const float*   f = (const float*)p;
    bool i32ok = true, f32ok = true;
    #pragma unroll
    for (int j = 0; j < 2; ++j) {
        const int idx = lane * 2 + j;
        const int32_t v = w[idx];
        i32ok &= (v >= -128 && v <= 127);
        const float x = f[idx];
        f32ok &= (x >= -128.0f && x <= 128.0f && x == truncf(x));
    }
    const uint32_t bi = __ballot_sync(0xFFFFFFFFu, i32ok);
    const uint32_t bf = __ballot_sync(0xFFFFFFFFu, f32ok);
    if (lane == 0) {
        const int dt = (bi == 0xFFFFFFFFu) ? 1 : ((bf == 0xFFFFFFFFu) ? 2 : 0);
        if (t < 32) g_dtA = dt; else g_dtB = dt;
    }
}

// ---------------------------------------------------------------------------
// Merged pre-pass. Blocks [0,4096): A. Blocks [4096,12288): B transpose.
// A: warp = one (8-row group, k-tile) -> writes one full 1KB swizzle group.
// B: 64x64 smem transpose; image layout identical to the proven R7 blocks.
// ---------------------------------------------------------------------------
__global__ void __launch_bounds__(256) conv_kernel(const void* __restrict__ A,
                                                   const void* __restrict__ B) {
    const int tid = threadIdx.x;
    if (blockIdx.x < 4096) {
        // ------------------------------ A ------------------------------
        const int w    = tid >> 5;
        const int lane = tid & 31;
        const int task = blockIdx.x * 8 + w;        // 32768 tasks
        const int mg = task >> 6;                   // 8-row group 0..511
        const int kt = task & 63;
        const int m  = mg * 8 + (lane >> 2);
        const int k  = kt * 64 + (lane & 3) * 16;
        const size_t src = (size_t)m * KDIM + k;
        const int dt = g_dtA;
        __nv_bfloat16 o[16];
        if (dt == 1) {
            const int32_t* p = (const int32_t*)A + src;
            #pragma unroll
            for (int j = 0; j < 16; ++j) o[j] = __float2bfloat16_rn((float)p[j]);
        } else if (dt == 2) {
            const float* p = (const float*)A + src;
            #pragma unroll
            for (int j = 0; j < 16; ++j) o[j] = __float2bfloat16_rn(p[j]);
        } else {
            uint4 v = *reinterpret_cast<const uint4*>((const int8_t*)A + src);
            const int8_t* b = reinterpret_cast<const int8_t*>(&v);
            #pragma unroll
            for (int j = 0; j < 16; ++j) o[j] = __float2bfloat16_rn((float)(int)b[j]);
        }
#if HAS_TCGEN05
        const uint32_t mt = (uint32_t)m >> 7, r = (uint32_t)m & 127;
        const uint32_t kl2 = ((uint32_t)(lane & 3) * 16) * 2;   // byte off in row
        uint8_t* blk = g_Aimg + (size_t)(mt * NKT + kt) * A_TILE;
        *reinterpret_cast<uint4*>(blk + sw128(r * 128 + kl2))      = *reinterpret_cast<uint4*>(&o[0]);
        *reinterpret_cast<uint4*>(blk + sw128(r * 128 + kl2 + 16)) = *reinterpret_cast<uint4*>(&o[8]);
#else
        __nv_bfloat16* dst = reinterpret_cast<__nv_bfloat16*>(g_Aimg) + src;
        *reinterpret_cast<uint4*>(dst)     = *reinterpret_cast<uint4*>(&o[0]);
        *reinterpret_cast<uint4*>(dst + 8) = *reinterpret_cast<uint4*>(&o[8]);
#endif
    } else {
        // ------------------------------ B ------------------------------
        __shared__ __nv_bfloat16 t[64][72];
        const int bb = blockIdx.x - 4096;
        const int n0 = (bb & 127) * 64;
        const int k0 = (bb >> 7) * 64;
        const int r  = tid >> 2;
        const int c  = (tid & 3) * 16;
        const int dt = g_dtB;

        const size_t src_off = (size_t)(k0 + r) * NDIM + n0 + c;
        __nv_bfloat16 o[16];
        if (dt == 1) {
            const int32_t* p = (const int32_t*)B + src_off;
            #pragma unroll
            for (int j = 0; j < 16; ++j) o[j] = __float2bfloat16_rn((float)p[j]);
        } else if (dt == 2) {
            const float* p = (const float*)B + src_off;
            #pragma unroll
            for (int j = 0; j < 16; ++j) o[j] = __float2bfloat16_rn(p[j]);
        } else {
            uint4 v = *reinterpret_cast<const uint4*>((const int8_t*)B + src_off);
            const int8_t* b = reinterpret_cast<const int8_t*>(&v);
            #pragma unroll
            for (int j = 0; j < 16; ++j) o[j] = __float2bfloat16_rn((float)(int)b[j]);
        }
        *reinterpret_cast<uint4*>(&t[r][c])     = *reinterpret_cast<uint4*>(&o[0]);
        *reinterpret_cast<uint4*>(&t[r][c + 8]) = *reinterpret_cast<uint4*>(&o[8]);
        __syncthreads();

        __nv_bfloat16 q[16];
        #pragma unroll
        for (int j = 0; j < 16; ++j) q[j] = t[c + j][r];     // Bt[n0+r][k0+c+j]

#if HAS_TCGEN05
        const uint32_t ng = n0 + r;
        const uint32_t nt = ng >> 8, nl = ng & 255;          // 256 N-rows / block
        const uint32_t kt = (uint32_t)k0 >> 6;
        uint8_t* blk = g_Bimg + (size_t)(nt * NKT + kt) * B_TILE;
        *reinterpret_cast<uint4*>(blk + sw128(nl * 128 + c * 2))      = *reinterpret_cast<uint4*>(&q[0]);
        *reinterpret_cast<uint4*>(blk + sw128(nl * 128 + c * 2 + 16)) = *reinterpret_cast<uint4*>(&q[8]);
#else
        __nv_bfloat16* dst = reinterpret_cast<__nv_bfloat16*>(g_Bimg) +
                             (size_t)(n0 + r) * KDIM + k0 + c;
        *reinterpret_cast<uint4*>(dst)     = *reinterpret_cast<uint4*>(&q[0]);
        *reinterpret_cast<uint4*>(dst + 8) = *reinterpret_cast<uint4*>(&q[8]);
#endif
    }
}

#if HAS_TCGEN05
DEVINL void mbar_init(uint32_t bar, uint32_t cnt) {
    asm volatile("mbarrier.init.shared.b64 [%0], %1;" :: "r"(bar), "r"(cnt) : "memory");
}
DEVINL void mbar_wait(uint32_t bar, uint32_t parity) {
    asm volatile(
        "{\n\t"
        ".reg .pred P;\n\t"
        "WAIT_%=:\n\t"
        "mbarrier.try_wait.parity.acquire.cta.shared::cta.b64 P, [%0], %1, 0x989680;\n\t"
        "@P bra.uni DONE_%=;\n\t"
        "bra.uni WAIT_%=;\n\t"
        "DONE_%=:\n\t"
        "}" :: "r"(bar), "r"(parity) : "memory");
}
DEVINL void mbar_expect_tx(uint32_t bar, uint32_t bytes) {
    asm volatile("mbarrier.arrive.expect_tx.shared.b64 _, [%0], %1;"
                 :: "r"(bar), "r"(bytes) : "memory");
}
DEVINL void bulk_g2s(uint32_t dst, const void* src, uint32_t bytes, uint32_t bar) {
    asm volatile(
        "cp.async.bulk.shared::cluster.global.mbarrier::complete_tx::bytes [%0], [%1], %2, [%3];"
        :: "r"(dst), "l"(src), "r"(bytes), "r"(bar) : "memory");
}
DEVINL void mma_bf16(uint32_t d, uint64_t ad, uint64_t bd, uint32_t idesc, uint32_t acc) {
    asm volatile(
        "{\n\t.reg .pred p;\n\t"
        "setp.ne.u32 p, %5, 0;\n\t"
        "tcgen05.mma.cta_group::1.kind::f16 [%0], %1, %2, %3, {%4, %4, %4, %4}, p;\n\t}"
        :: "r"(d), "l"(ad), "l"(bd), "r"(idesc), "r"(0u), "r"(acc) : "memory");
}
DEVINL void tc_commit(uint32_t bar) {
    asm volatile("tcgen05.commit.cta_group::1.mbarrier::arrive::one.shared::cluster.b64 [%0];"
                 :: "r"(bar) : "memory");
}
DEVINL void tc_fence_after() { asm volatile("tcgen05.fence::after_thread_sync;" ::: "memory"); }
DEVINL void tc_wait_ld() { asm volatile("tcgen05.wait::ld.sync.aligned;" ::: "memory"); }

#define TC_LD_X32(r, addr)                                                     \
    asm volatile(                                                              \
        "tcgen05.ld.sync.aligned.32x32b.x32.b32 "                              \
        "{%0, %1, %2, %3, %4, %5, %6, %7, "                                    \
        " %8, %9, %10, %11, %12, %13, %14, %15, "                              \
        " %16, %17, %18, %19, %20, %21, %22, %23, "                            \
        " %24, %25, %26, %27, %28, %29, %30, %31}, [%32];"                     \
        : "=r"((r)[0]),  "=r"((r)[1]),  "=r"((r)[2]),  "=r"((r)[3]),           \
          "=r"((r)[4]),  "=r"((r)[5]),  "=r"((r)[6]),  "=r"((r)[7]),           \
          "=r"((r)[8]),  "=r"((r)[9]),  "=r"((r)[10]), "=r"((r)[11]),          \
          "=r"((r)[12]), "=r"((r)[13]), "=r"((r)[14]), "=r"((r)[15]),          \
          "=r"((r)[16]), "=r"((r)[17]), "=r"((r)[18]), "=r"((r)[19]),          \
          "=r"((r)[20]), "=r"((r)[21]), "=r"((r)[22]), "=r"((r)[23]),          \
          "=r"((r)[24]), "=r"((r)[25]), "=r"((r)[26]), "=r"((r)[27]),          \
          "=r"((r)[28]), "=r"((r)[29]), "=r"((r)[30]), "=r"((r)[31])           \
        : "r"(addr))
#else
DEVINL void cp_async16(uint32_t dst, const void* src) {
    asm volatile("cp.async.cg.shared.global [%0], [%1], 16;" :: "r"(dst), "l"(src) : "memory");
}
DEVINL void cp_commit() { asm volatile("cp.async.commit_group;" ::: "memory"); }
template <int N> DEVINL void cp_wait() {
    asm volatile("cp.async.wait_group %0;" :: "n"(N) : "memory");
}
DEVINL void ldsm_x4(uint32_t (&r)[4], uint32_t addr) {
    asm volatile("ldmatrix.sync.aligned.m8n8.x4.shared.b16 {%0,%1,%2,%3}, [%4];"
                 : "=r"(r[0]), "=r"(r[1]), "=r"(r[2]), "=r"(r[3]) : "r"(addr));
}
DEVINL void mma16816(float (&d)[4], const uint32_t (&a)[4], uint32_t b0, uint32_t b1) {
    asm volatile(
        "mma.sync.aligned.m16n8k16.row.col.f32.bf16.bf16.f32 "
        "{%0,%1,%2,%3}, {%4,%5,%6,%7}, {%8,%9}, {%0,%1,%2,%3};"
        : "+f"(d[0]), "+f"(d[1]), "+f"(d[2]), "+f"(d[3])
        : "r"(a[0]), "r"(a[1]), "r"(a[2]), "r"(a[3]), "r"(b0), "r"(b1));
}
#endif

__global__ void __launch_bounds__(THREADS, 1)
gemm_kernel(const float* __restrict__ scale, float* __restrict__ out)
{
    extern __shared__ char smem_raw[];

#if HAS_TCGEN05
    // =========================================================================
    // Single-CTA 256x256 tile, cg1 MMAs, TMEM fully used (512 cols).
    // Stage = A0 16KB + A1 16KB + B 32KB; 3 bulk copies, 3 stages.
    // =========================================================================
    const uint32_t sb_raw = smem_u32(smem_raw);
    const uint32_t sb = (sb_raw + 1023u) & ~1023u;
    char* smem = smem_raw + (sb - sb_raw);

    const int tid = threadIdx.x;
    const int wid = tid >> 5;

    const int mt = blockIdx.x & 15;   // m-fastest raster: A images L2-warm
    const int nt = blockIdx.x >> 4;
    const int m0 = mt * 256;
    const int n0 = nt * 256;

    const uint32_t bar_full0  = sb + OFF_BAR;        // 3 x 8B
    const uint32_t bar_empty0 = sb + OFF_BAR + 24;   // 3 x 8B
    const uint32_t bar_done   = sb + OFF_BAR + 48;
    const uint32_t tmem_ptr   = sb + OFF_BAR + 56;
    float* s_scale = reinterpret_cast<float*>(smem + OFF_SCALE);

    if (tid == 0) {
        #pragma unroll
        for (int s = 0; s < NSTAGE; ++s) {
            mbar_init(bar_full0 + s * 8, 1);
            mbar_init(bar_empty0 + s * 8, 1);
        }
        mbar_init(bar_done, 1);
    }
    if (wid == 0) {
        asm volatile("tcgen05.alloc.cta_group::1.sync.aligned.shared::cta.b32 [%0], %1;"
                     :: "r"(tmem_ptr), "r"(TMEM_COLS) : "memory");
    }
    if (tid < 256) s_scale[tid] = scale[n0 + tid];
    __syncthreads();

    uint32_t tmem;
    asm volatile("ld.shared.b32 %0, [%1];" : "=r"(tmem) : "r"(tmem_ptr));

    if (tid == 0) {
        // ---- consumer: wait full, 16 MMAs (2 mhalf x 2 nhalf x 4 q) ----
        int s = 0, ph = 0;
        for (int kt = 0; kt < NKT; ++kt) {
            mbar_wait(bar_full0 + s * 8, ph);
            const uint32_t stg = sb + (uint32_t)s * STAGE_BYTES;
            #pragma unroll
            for (int mh = 0; mh < 2; ++mh) {
                const uint64_t adesc = DESC_BASE_K |
                    (((stg + (uint32_t)mh * A_TILE) >> 4) & 0x3FFFu);
                #pragma unroll
                for (int nh = 0; nh < 2; ++nh) {
                    const uint64_t bdesc = DESC_BASE_K |
                        (((stg + 2 * A_TILE + (uint32_t)nh * 16384u) >> 4) & 0x3FFFu);
                    const uint32_t dreg = tmem + mh * 256 + nh * 128;
                    #pragma unroll
                    for (int q = 0; q < 4; ++q) {
                        mma_bf16(dreg,
                                 adesc + (uint64_t)(q * 2),
                                 bdesc + (uint64_t)(q * 2),
                                 IDESC,
                                 (kt > 0 || q > 0) ? 1u : 0u);
                    }
                }
            }
            tc_commit(bar_empty0 + s * 8);
            if (++s == NSTAGE) { s = 0; ph ^= 1; }
        }
        tc_commit(bar_done);
    } else if (tid == 32) {
        // ---- producer: wait empty, expect_tx 64KB, 3 bulk copies ----
        const uint8_t* gA0 = g_Aimg + (size_t)((mt * 2 + 0) * NKT) * A_TILE;
        const uint8_t* gA1 = g_Aimg + (size_t)((mt * 2 + 1) * NKT) * A_TILE;
        const uint8_t* gB  = g_Bimg + (size_t)(nt * NKT) * B_TILE;
        int s = 0, ph = 1;   // fresh barrier: parity-1 wait passes immediately
        for (int kt = 0; kt < NKT; ++kt) {
            mbar_wait(bar_empty0 + s * 8, ph);
            const uint32_t stg  = sb + (uint32_t)s * STAGE_BYTES;
            const uint32_t barf = bar_full0 + s * 8;
            mbar_expect_tx(barf, (uint32_t)STAGE_BYTES);
            bulk_g2s(stg,              gA0 + (size_t)kt * A_TILE, (uint32_t)A_TILE, barf);
            bulk_g2s(stg + A_TILE,     gA1 + (size_t)kt * A_TILE, (uint32_t)A_TILE, barf);
            bulk_g2s(stg + 2 * A_TILE, gB  + (size_t)kt * B_TILE, (uint32_t)B_TILE, barf);
            if (++s == NSTAGE) { s = 0; ph ^= 1; }
        }
    }

    // ---- epilogue: 16 warps cover 2 mhalves x 2 colgroups x 4 subparts ----
    mbar_wait(bar_done, 0);
    tc_fence_after();

    const int lane = tid & 31;
    const int g    = wid >> 2;          // 0..3: mh = g>>1, colgroup = g&1
    const int sp   = wid & 3;           // TMEM subpartition
    const int mh   = g >> 1;
    const int cg   = g & 1;
    const int mrow = m0 + mh * 128 + sp * 32 + lane;
    float* orow = out + (size_t)mrow * NDIM + n0 + cg * 128;

    #pragma unroll
    for (int blk = 0; blk < 4; ++blk) {
        uint32_t r[32];
        TC_LD_X32(r, tmem + mh * 256 + cg * 128 + blk * 32);
        tc_wait_ld();
        const float* sc = s_scale + cg * 128 + blk * 32;
        #pragma unroll
        for (int i = 0; i < 32; i += 4) {
            float4 v;
            v.x = __uint_as_float(r[i + 0]) * sc[i + 0];
            v.y = __uint_as_float(r[i + 1]) * sc[i + 1];
            v.z = __uint_as_float(r[i + 2]) * sc[i + 2];
            v.w = __uint_as_float(r[i + 3]) * sc[i + 3];
            *reinterpret_cast<float4*>(orow + blk * 32 + i) = v;
        }
    }

    __syncthreads();
    if (wid == 0) {
        asm volatile("tcgen05.dealloc.cta_group::1.sync.aligned.b32 %0, %1;"
                     :: "r"(tmem), "r"(TMEM_COLS));
    }

#else
    // =========================================================================
    // Fallback (compute_103 phase): mma.sync engine, two 128x256 passes.
    // =========================================================================
    constexpr int BM = 128;
    constexpr int BN = 256;
    constexpr int KC = 32;
    constexpr int NKT2 = KDIM / KC;
    constexpr int RSB = 80;
    constexpr int SA_BYTES = BM * RSB;
    constexpr int SB_BYTES = BN * RSB;
    constexpr int STAGE = SA_BYTES + SB_BYTES;

    const uint32_t sb = smem_u32(smem_raw);
    const int tid  = threadIdx.x;
    const int wid  = tid >> 5;
    const int lane = tid & 31;

    const int mt = blockIdx.x & 15;
    const int nt = blockIdx.x >> 4;
    const int n0 = nt * BN;

    const int wm = (wid >> 2) * 32;
    const int wn = (wid & 3) * 64;
    const int lr = lane & 15;
    const int lh = (lane >> 4) * 16;

    for (int pass = 0; pass < 2; ++pass) {
        const int m0 = mt * 256 + pass * BM;
        const __nv_bfloat16* gA = reinterpret_cast<const __nv_bfloat16*>(g_Aimg) + (size_t)m0 * KDIM;
        const __nv_bfloat16* gB = reinterpret_cast<const __nv_bfloat16*>(g_Bimg) + (size_t)n0 * KDIM;

        auto fill = [&](int buf, int kt) {
            const uint32_t base = sb + buf * STAGE;
            #pragma unroll
            for (int j = 0; j < 3; ++j) {
                const int q = tid + j * THREADS;
                if (q < 512) {
                    const int r = q >> 2, c = q & 3;
                    cp_async16(base + r * RSB + c * 16, gA + (size_t)r * KDIM + kt * KC + c * 8);
                } else {
                    const int qb = q - 512;
                    const int r = qb >> 2, c = qb & 3;
                    cp_async16(base + SA_BYTES + r * RSB + c * 16,
                               gB + (size_t)r * KDIM + kt * KC + c * 8);
                }
            }
            cp_commit();
        };

        float acc[2][8][4];
        #pragma unroll
        for (int mi = 0; mi < 2; ++mi)
            #pragma unroll
            for (int nf = 0; nf < 8; ++nf)
                #pragma unroll
                for (int k = 0; k < 4; ++k) acc[mi][nf][k] = 0.0f;

        fill(0, 0);

        for (int kt = 0; kt < NKT2; ++kt) {
            if (kt + 1 < NKT2) fill((kt + 1) & 1, kt + 1);
            if (kt + 1 < NKT2) cp_wait<1>(); else cp_wait<0>();
            __syncthreads();

            const uint32_t aB = sb + (kt & 1) * STAGE;
            const uint32_t bB = aB + SA_BYTES;

            #pragma unroll
            for (int s = 0; s < 2; ++s) {
                const int kb = s * 32;
                uint32_t av[2][4];
                #pragma unroll
                for (int mi = 0; mi < 2; ++mi)
                    ldsm_x4(av[mi], aB + (wm + mi * 16 + lr) * RSB + kb + lh);
                uint32_t bv[4][4];
                #pragma unroll
                for (int nb = 0; nb < 4; ++nb)
                    ldsm_x4(bv[nb], bB + (wn + nb * 16 + lr) * RSB + kb + lh);
                #pragma unroll
                for (int mi = 0; mi < 2; ++mi) {
                    #pragma unroll
                    for (int nb = 0; nb < 4; ++nb) {
                        mma16816(acc[mi][nb * 2 + 0], av[mi], bv[nb][0], bv[nb][2]);
                        mma16816(acc[mi][nb * 2 + 1], av[mi], bv[nb][1], bv[nb][3]);
                    }
                }
            }
            __syncthreads();
        }

        const int gr = lane >> 2;
        const int t4 = lane & 3;
        #pragma unroll
        for (int mi = 0; mi < 2; ++mi) {
            const int mrow = m0 + wm + mi * 16 + gr;
            #pragma unroll
            for (int nf = 0; nf < 8; ++nf) {
                const int ncol = n0 + wn + nf * 8 + t4 * 2;
                const float s0 = __ldg(&scale[ncol]);
                const float s1 = __ldg(&scale[ncol + 1]);
                float2 v0 = make_float2(acc[mi][nf][0] * s0, acc[mi][nf][1] * s1);
                float2 v1 = make_float2(acc[mi][nf][2] * s0, acc[mi][nf][3] * s1);
                *reinterpret_cast<float2*>(out + (size_t)mrow * NDIM + ncol) = v0;
                *reinterpret_cast<float2*>(out + (size_t)(mrow + 8) * NDIM + ncol) = v1;
            }
        }
        __syncthreads();
    }
#endif
}

} // namespace s8gemm

extern "C" void kernel_launch(void* const* d_in, const int* in_sizes, int n_in,
                              void* d_out, int out_size)
{
    using namespace s8gemm;

    const void* pa = nullptr;
    const void* pb = nullptr;
    const float* ps = nullptr;
    for (int i = 0; i < n_in; ++i) {
        if (in_sizes[i] == MDIM * KDIM)      pa = d_in[i];
        else if (in_sizes[i] == KDIM * NDIM) pb = d_in[i];
        else if (in_sizes[i] == NDIM)        ps = (const float*)d_in[i];
    }
    if (!pa) pa = d_in[0];
    if (!pb) pb = d_in[1];
    if (!ps) ps = (const float*)d_in[2];
    float* out = (float*)d_out;
    (void)out_size;

    detect_kernel<<<1, 64>>>(pa, pb);
    conv_kernel<<<12288, 256>>>(pa, pb);

    cudaFuncSetAttribute(gemm_kernel,
                         cudaFuncAttributeMaxDynamicSharedMemorySize, SMEM_ALLOC);
    gemm_kernel<<<CTAS, THREADS, SMEM_ALLOC>>>(ps, out);
}

// round 11
// speedup vs baseline: 1.3530x; 1.1913x over previous
#include <cuda_runtime.h>
#include <cuda_bf16.h>
#include <cstdint>

#define DEVINL __device__ __forceinline__

#if defined(__CUDA_ARCH__) && \
    (defined(__CUDA_ARCH_FEAT_SM103_ALL) || defined(__CUDA_ARCH_FEAT_SM100_ALL) || \
     defined(__CUDA_ARCH_FEAT_SM101_ALL) || defined(__CUDA_ARCH_SPECIFIC__) || \
     defined(__CUDA_ARCH_FAMILY_SPECIFIC__))
#define HAS_TCGEN05 1
#else
#define HAS_TCGEN05 0
#endif

namespace s8gemm {

constexpr int MDIM = 4096;
constexpr int KDIM = 4096;
constexpr int NDIM = 8192;

// ---- tcgen05 tiling: single CTA computes 256(M) x 256(N) ----
constexpr int NSTAGE = 3;
constexpr int NKT = KDIM / 64;    // 64 k-tiles (64 bf16 = 128B rows)

constexpr int A_TILE = 128 * 128;              // 16 KB per 128-row A image block
constexpr int B_TILE = 256 * 128;              // 32 KB per (nt,kt) B image block
constexpr int STAGE_BYTES = 2 * A_TILE + B_TILE;   // 65536
constexpr int OFF_BAR   = NSTAGE * STAGE_BYTES;    // 196608
constexpr int OFF_SCALE = OFF_BAR + 64;
constexpr int SMEM_ALLOC = OFF_SCALE + 256 * 4 + 1024;   // ~198.7 KB

constexpr int TMEM_COLS = 512;    // 2 M-halves x 256 fp32 cols
constexpr int MT = MDIM / 128;    // 32 A image blocks
constexpr int NTL = NDIM / 256;   // 32
constexpr int CTAS = (MDIM / 256) * NTL;   // 512
constexpr int THREADS = 512;

// cg1 kind::f16 idesc: F32 acc, BF16 x BF16, N=128, M=128 (both K-major).
constexpr uint32_t IDESC =
      (1u << 4) | (1u << 7) | (1u << 10)
    | ((128u / 8u) << 17) | ((128u / 16u) << 24);

// K-major SW128 SMEM descriptor (Blackwell version=1): LBO=1, SBO=64.
constexpr uint64_t DESC_BASE_K =
      (uint64_t(2) << 61) | (uint64_t(1) << 46) | (uint64_t(64) << 32) | (uint64_t(1) << 16);

// Scratch images (tcgen05 build):
//   A block (mt128*NKT + kt): 16KB swizzled [128 rows x 128B], mt128 = 0..31.
//   B block (nt*NKT + kt):    32KB swizzled [256 N-rows x 128B].
// Fallback build: linear bf16 A[M][K] / Bt[N][K].
__device__ __align__(1024) uint8_t g_Aimg[(size_t)MT * NKT * A_TILE];    // 32 MB
__device__ __align__(1024) uint8_t g_Bimg[(size_t)NTL * NKT * B_TILE];   // 64 MB

DEVINL uint32_t smem_u32(const void* p) {
    uint32_t a;
    asm("{ .reg .u64 t; cvta.to.shared.u64 t, %1; cvt.u32.u64 %0, t; }" : "=r"(a) : "l"(p));
    return a;
}
DEVINL uint32_t sw128(uint32_t off) { return off ^ ((off >> 3) & 0x70u); }

// ---------------------------------------------------------------------------
// Per-warp dtype classification from the input's first 64 words (L2-broadcast;
// 2 loads + 2 ballots). 0=int8-packed, 1=int32-widened, 2=fp32-widened.
// ---------------------------------------------------------------------------
DEVINL int classify_warp(const void* p) {
    const int lane = threadIdx.x & 31;
    const int32_t* w = (const int32_t*)p;
    const float*   f = (const float*)p;
    bool i32ok = true, f32ok = true;
    #pragma unroll
    for (int j = 0; j < 2; ++j) {
        const int idx = lane * 2 + j;
        const int32_t v = w[idx];
        i32ok &= (v >= -128 && v <= 127);
        const float x = f[idx];
        f32ok &= (x >= -128.0f && x <= 128.0f && x == truncf(x));
    }
    const uint32_t bi = __ballot_sync(0xFFFFFFFFu, i32ok);
    const uint32_t bf = __ballot_sync(0xFFFFFFFFu, f32ok);
    return (bi == 0xFFFFFFFFu) ? 1 : ((bf == 0xFFFFFFFFu) ? 2 : 0);
}

// ---------------------------------------------------------------------------
// Exact bf16 packing for int8-range integral values: f32->bf16 rn == truncation
// (mantissa <= 8 bits -> low 16 f32 bits are zero), so PRMT picks the top
// halves of two f32 words. 1 op per pair instead of 2 F2FP.
// ---------------------------------------------------------------------------
DEVINL uint32_t pack_bf16x2(float f0, float f1) {
    return __byte_perm(__float_as_uint(f0), __float_as_uint(f1), 0x7632);
}

// Convert 16 logical int8 elems at element index idx (16B-chunk aligned) of
// input P (dtype dt) into 8 bf16x2 words. Explicit vector loads.
DEVINL void conv16(const void* __restrict__ P, size_t idx, int dt, uint32_t (&u)[8]) {
    if (dt == 1) {
        const uint4* p = reinterpret_cast<const uint4*>((const int32_t*)P + idx);
        #pragma unroll
        for (int q = 0; q < 4; ++q) {
            const uint4 w = p[q];
            u[q * 2 + 0] = pack_bf16x2((float)(int)w.x, (float)(int)w.y);
            u[q * 2 + 1] = pack_bf16x2((float)(int)w.z, (float)(int)w.w);
        }
    } else if (dt == 2) {
        const float4* p = reinterpret_cast<const float4*>((const float*)P + idx);
        #pragma unroll
        for (int q = 0; q < 4; ++q) {
            const float4 w = p[q];
            u[q * 2 + 0] = pack_bf16x2(w.x, w.y);
            u[q * 2 + 1] = pack_bf16x2(w.z, w.w);
        }
    } else {
        const uint4 v = *reinterpret_cast<const uint4*>((const int8_t*)P + idx);
        const int8_t* b = reinterpret_cast<const int8_t*>(&v);
        #pragma unroll
        for (int j = 0; j < 8; ++j)
            u[j] = pack_bf16x2((float)(int)b[2 * j], (float)(int)b[2 * j + 1]);
    }
}

// ---------------------------------------------------------------------------
// Merged pre-pass. Blocks [0,4096): A. Blocks [4096,12288): B transpose.
// A: warp = one (8-row group, k-tile) -> writes one full 1KB swizzle group.
// B: 64x64 smem transpose; image layout identical to the proven blocks.
// ---------------------------------------------------------------------------
__global__ void __launch_bounds__(256) conv_kernel(const void* __restrict__ A,
                                                   const void* __restrict__ B) {
    const int tid = threadIdx.x;
    if (blockIdx.x < 4096) {
        // ------------------------------ A ------------------------------
        const int dt   = classify_warp(A);
        const int w    = tid >> 5;
        const int lane = tid & 31;
        const int task = blockIdx.x * 8 + w;        // 32768 tasks
        const int mg = task >> 6;                   // 8-row group 0..511
        const int kt = task & 63;
        const int m  = mg * 8 + (lane >> 2);
        const int k  = kt * 64 + (lane & 3) * 16;
        uint32_t u[8];
        conv16(A, (size_t)m * KDIM + k, dt, u);
#if HAS_TCGEN05
        const uint32_t mt = (uint32_t)m >> 7, r = (uint32_t)m & 127;
        const uint32_t kl2 = (uint32_t)(lane & 3) * 32;   // byte off in 128B row
        uint8_t* blk = g_Aimg + (size_t)(mt * NKT + kt) * A_TILE;
        *reinterpret_cast<uint4*>(blk + sw128(r * 128 + kl2))      = *reinterpret_cast<uint4*>(&u[0]);
        *reinterpret_cast<uint4*>(blk + sw128(r * 128 + kl2 + 16)) = *reinterpret_cast<uint4*>(&u[4]);
#else
        __nv_bfloat16* dst = reinterpret_cast<__nv_bfloat16*>(g_Aimg) + (size_t)m * KDIM + k;
        *reinterpret_cast<uint4*>(dst)     = *reinterpret_cast<uint4*>(&u[0]);
        *reinterpret_cast<uint4*>(dst + 8) = *reinterpret_cast<uint4*>(&u[4]);
#endif
    } else {
        // ------------------------------ B ------------------------------
        __shared__ __nv_bfloat16 t[64][72];   // 144B rows: 16B-aligned vec I/O
        const int dt = classify_warp(B);
        const int bb = blockIdx.x - 4096;
        const int n0 = (bb & 127) * 64;
        const int k0 = (bb >> 7) * 64;
        const int r  = tid >> 2;
        const int c  = (tid & 3) * 16;

        uint32_t u[8];
        conv16(B, (size_t)(k0 + r) * NDIM + n0 + c, dt, u);
        *reinterpret_cast<uint4*>(&t[r][c])     = *reinterpret_cast<uint4*>(&u[0]);
        *reinterpret_cast<uint4*>(&t[r][c + 8]) = *reinterpret_cast<uint4*>(&u[4]);
        __syncthreads();

        __nv_bfloat16 q[16];
        #pragma unroll
        for (int j = 0; j < 16; ++j) q[j] = t[c + j][r];     // Bt[n0+r][k0+c+j]

#if HAS_TCGEN05
        const uint32_t ng = n0 + r;
        const uint32_t nt = ng >> 8, nl = ng & 255;          // 256 N-rows / block
        const uint32_t kt = (uint32_t)k0 >> 6;
        uint8_t* blk = g_Bimg + (size_t)(nt * NKT + kt) * B_TILE;
        *reinterpret_cast<uint4*>(blk + sw128(nl * 128 + c * 2))      = *reinterpret_cast<uint4*>(&q[0]);
        *reinterpret_cast<uint4*>(blk + sw128(nl * 128 + c * 2 + 16)) = *reinterpret_cast<uint4*>(&q[8]);
#else
        __nv_bfloat16* dst = reinterpret_cast<__nv_bfloat16*>(g_Bimg) +
                             (size_t)(n0 + r) * KDIM + k0 + c;
        *reinterpret_cast<uint4*>(dst)     = *reinterpret_cast<uint4*>(&q[0]);
        *reinterpret_cast<uint4*>(dst + 8) = *reinterpret_cast<uint4*>(&q[8]);
#endif
    }
}

#if HAS_TCGEN05
DEVINL void mbar_init(uint32_t bar, uint32_t cnt) {
    asm volatile("mbarrier.init.shared.b64 [%0], %1;" :: "r"(bar), "r"(cnt) : "memory");
}
DEVINL void mbar_wait(uint32_t bar, uint32_t parity) {
    asm volatile(
        "{\n\t"
        ".reg .pred P;\n\t"
        "WAIT_%=:\n\t"
        "mbarrier.try_wait.parity.acquire.cta.shared::cta.b64 P, [%0], %1, 0x989680;\n\t"
        "@P bra.uni DONE_%=;\n\t"
        "bra.uni WAIT_%=;\n\t"
        "DONE_%=:\n\t"
        "}" :: "r"(bar), "r"(parity) : "memory");
}
DEVINL void mbar_expect_tx(uint32_t bar, uint32_t bytes) {
    asm volatile("mbarrier.arrive.expect_tx.shared.b64 _, [%0], %1;"
                 :: "r"(bar), "r"(bytes) : "memory");
}
DEVINL void bulk_g2s(uint32_t dst, const void* src, uint32_t bytes, uint32_t bar) {
    asm volatile(
        "cp.async.bulk.shared::cluster.global.mbarrier::complete_tx::bytes [%0], [%1], %2, [%3];"
        :: "r"(dst), "l"(src), "r"(bytes), "r"(bar) : "memory");
}
DEVINL void mma_bf16(uint32_t d, uint64_t ad, uint64_t bd, uint32_t idesc, uint32_t acc) {
    asm volatile(
        "{\n\t.reg .pred p;\n\t"
        "setp.ne.u32 p, %5, 0;\n\t"
        "tcgen05.mma.cta_group::1.kind::f16 [%0], %1, %2, %3, {%4, %4, %4, %4}, p;\n\t}"
        :: "r"(d), "l"(ad), "l"(bd), "r"(idesc), "r"(0u), "r"(acc) : "memory");
}
DEVINL void tc_commit(uint32_t bar) {
    asm volatile("tcgen05.commit.cta_group::1.mbarrier::arrive::one.shared::cluster.b64 [%0];"
                 :: "r"(bar) : "memory");
}
DEVINL void tc_fence_after() { asm volatile("tcgen05.fence::after_thread_sync;" ::: "memory"); }
DEVINL void tc_wait_ld() { asm volatile("tcgen05.wait::ld.sync.aligned;" ::: "memory"); }

#define TC_LD_X32(r, addr)                                                     \
    asm volatile(                                                              \
        "tcgen05.ld.sync.aligned.32x32b.x32.b32 "                              \
        "{%0, %1, %2, %3, %4, %5, %6, %7, "                                    \
        " %8, %9, %10, %11, %12, %13, %14, %15, "                              \
        " %16, %17, %18, %19, %20, %21, %22, %23, "                            \
        " %24, %25, %26, %27, %28, %29, %30, %31}, [%32];"                     \
        : "=r"((r)[0]),  "=r"((r)[1]),  "=r"((r)[2]),  "=r"((r)[3]),           \
          "=r"((r)[4]),  "=r"((r)[5]),  "=r"((r)[6]),  "=r"((r)[7]),           \
          "=r"((r)[8]),  "=r"((r)[9]),  "=r"((r)[10]), "=r"((r)[11]),          \
          "=r"((r)[12]), "=r"((r)[13]), "=r"((r)[14]), "=r"((r)[15]),          \
          "=r"((r)[16]), "=r"((r)[17]), "=r"((r)[18]), "=r"((r)[19]),          \
          "=r"((r)[20]), "=r"((r)[21]), "=r"((r)[22]), "=r"((r)[23]),          \
          "=r"((r)[24]), "=r"((r)[25]), "=r"((r)[26]), "=r"((r)[27]),          \
          "=r"((r)[28]), "=r"((r)[29]), "=r"((r)[30]), "=r"((r)[31])           \
        : "r"(addr))
#else
DEVINL void cp_async16(uint32_t dst, const void* src) {
    asm volatile("cp.async.cg.shared.global [%0], [%1], 16;" :: "r"(dst), "l"(src) : "memory");
}
DEVINL void cp_commit() { asm volatile("cp.async.commit_group;" ::: "memory"); }
template <int N> DEVINL void cp_wait() {
    asm volatile("cp.async.wait_group %0;" :: "n"(N) : "memory");
}
DEVINL void ldsm_x4(uint32_t (&r)[4], uint32_t addr) {
    asm volatile("ldmatrix.sync.aligned.m8n8.x4.shared.b16 {%0,%1,%2,%3}, [%4];"
                 : "=r"(r[0]), "=r"(r[1]), "=r"(r[2]), "=r"(r[3]) : "r"(addr));
}
DEVINL void mma16816(float (&d)[4], const uint32_t (&a)[4], uint32_t b0, uint32_t b1) {
    asm volatile(
        "mma.sync.aligned.m16n8k16.row.col.f32.bf16.bf16.f32 "
        "{%0,%1,%2,%3}, {%4,%5,%6,%7}, {%8,%9}, {%0,%1,%2,%3};"
        : "+f"(d[0]), "+f"(d[1]), "+f"(d[2]), "+f"(d[3])
        : "r"(a[0]), "r"(a[1]), "r"(a[2]), "r"(a[3]), "r"(b0), "r"(b1));
}
#endif

__global__ void __launch_bounds__(THREADS, 1)
gemm_kernel(const float* __restrict__ scale, float* __restrict__ out)
{
    extern __shared__ char smem_raw[];

#if HAS_TCGEN05
    // =========================================================================
    // Single-CTA 256x256 tile, cg1 MMAs, TMEM fully used (512 cols).
    // Stage = A0 16KB + A1 16KB + B 32KB; 3 bulk copies, 3 stages.
    // =========================================================================
    const uint32_t sb_raw = smem_u32(smem_raw);
    const uint32_t sb = (sb_raw + 1023u) & ~1023u;
    char* smem = smem_raw + (sb - sb_raw);

    const int tid = threadIdx.x;
    const int wid = tid >> 5;

    const int mt = blockIdx.x & 15;   // m-fastest raster: A images L2-warm
    const int nt = blockIdx.x >> 4;
    const int m0 = mt * 256;
    const int n0 = nt * 256;

    const uint32_t bar_full0  = sb + OFF_BAR;        // 3 x 8B
    const uint32_t bar_empty0 = sb + OFF_BAR + 24;   // 3 x 8B
    const uint32_t bar_done   = sb + OFF_BAR + 48;
    const uint32_t tmem_ptr   = sb + OFF_BAR + 56;
    float* s_scale = reinterpret_cast<float*>(smem + OFF_SCALE);

    if (tid == 0) {
        #pragma unroll
        for (int s = 0; s < NSTAGE; ++s) {
            mbar_init(bar_full0 + s * 8, 1);
            mbar_init(bar_empty0 + s * 8, 1);
        }
        mbar_init(bar_done, 1);
    }
    if (wid == 0) {
        asm volatile("tcgen05.alloc.cta_group::1.sync.aligned.shared::cta.b32 [%0], %1;"
                     :: "r"(tmem_ptr), "r"(TMEM_COLS) : "memory");
    }
    if (tid < 256) s_scale[tid] = scale[n0 + tid];
    __syncthreads();

    uint32_t tmem;
    asm volatile("ld.shared.b32 %0, [%1];" : "=r"(tmem) : "r"(tmem_ptr));

    if (tid == 0) {
        // ---- consumer: wait full, 16 MMAs (2 mhalf x 2 nhalf x 4 q) ----
        int s = 0, ph = 0;
        for (int kt = 0; kt < NKT; ++kt) {
            mbar_wait(bar_full0 + s * 8, ph);
            const uint32_t stg = sb + (uint32_t)s * STAGE_BYTES;
            #pragma unroll
            for (int mh = 0; mh < 2; ++mh) {
                const uint64_t adesc = DESC_BASE_K |
                    (((stg + (uint32_t)mh * A_TILE) >> 4) & 0x3FFFu);
                #pragma unroll
                for (int nh = 0; nh < 2; ++nh) {
                    const uint64_t bdesc = DESC_BASE_K |
                        (((stg + 2 * A_TILE + (uint32_t)nh * 16384u) >> 4) & 0x3FFFu);
                    const uint32_t dreg = tmem + mh * 256 + nh * 128;
                    #pragma unroll
                    for (int q = 0; q < 4; ++q) {
                        mma_bf16(dreg,
                                 adesc + (uint64_t)(q * 2),
                                 bdesc + (uint64_t)(q * 2),
                                 IDESC,
                                 (kt > 0 || q > 0) ? 1u : 0u);
                    }
                }
            }
            tc_commit(bar_empty0 + s * 8);
            if (++s == NSTAGE) { s = 0; ph ^= 1; }
        }
        tc_commit(bar_done);
    } else if (tid == 32) {
        // ---- producer: wait empty, expect_tx 64KB, 3 bulk copies ----
        const uint8_t* gA0 = g_Aimg + (size_t)((mt * 2 + 0) * NKT) * A_TILE;
        const uint8_t* gA1 = g_Aimg + (size_t)((mt * 2 + 1) * NKT) * A_TILE;
        const uint8_t* gB  = g_Bimg + (size_t)(nt * NKT) * B_TILE;
        int s = 0, ph = 1;   // fresh barrier: parity-1 wait passes immediately
        for (int kt = 0; kt < NKT; ++kt) {
            mbar_wait(bar_empty0 + s * 8, ph);
            const uint32_t stg  = sb + (uint32_t)s * STAGE_BYTES;
            const uint32_t barf = bar_full0 + s * 8;
            mbar_expect_tx(barf, (uint32_t)STAGE_BYTES);
            bulk_g2s(stg,              gA0 + (size_t)kt * A_TILE, (uint32_t)A_TILE, barf);
            bulk_g2s(stg + A_TILE,     gA1 + (size_t)kt * A_TILE, (uint32_t)A_TILE, barf);
            bulk_g2s(stg + 2 * A_TILE, gB  + (size_t)kt * B_TILE, (uint32_t)B_TILE, barf);
            if (++s == NSTAGE) { s = 0; ph ^= 1; }
        }
    }

    // ---- epilogue: 16 warps cover 2 mhalves x 2 colgroups x 4 subparts ----
    mbar_wait(bar_done, 0);
    tc_fence_after();

    const int lane = tid & 31;
    const int g    = wid >> 2;          // 0..3: mh = g>>1, colgroup = g&1
    const int sp   = wid & 3;           // TMEM subpartition
    const int mh   = g >> 1;
    const int cg   = g & 1;
    const int mrow = m0 + mh * 128 + sp * 32 + lane;
    float* orow = out + (size_t)mrow * NDIM + n0 + cg * 128;

    #pragma unroll
    for (int blk = 0; blk < 4; ++blk) {
        uint32_t r[32];
        TC_LD_X32(r, tmem + mh * 256 + cg * 128 + blk * 32);
        tc_wait_ld();
        const float* sc = s_scale + cg * 128 + blk * 32;
        #pragma unroll
        for (int i = 0; i < 32; i += 4) {
            float4 v;
            v.x = __uint_as_float(r[i + 0]) * sc[i + 0];
            v.y = __uint_as_float(r[i + 1]) * sc[i + 1];
            v.z = __uint_as_float(r[i + 2]) * sc[i + 2];
            v.w = __uint_as_float(r[i + 3]) * sc[i + 3];
            *reinterpret_cast<float4*>(orow + blk * 32 + i) = v;
        }
    }

    __syncthreads();
    if (wid == 0) {
        asm volatile("tcgen05.dealloc.cta_group::1.sync.aligned.b32 %0, %1;"
                     :: "r"(tmem), "r"(TMEM_COLS));
    }

#else
    // =========================================================================
    // Fallback (compute_103 phase): mma.sync engine, two 128x256 passes.
    // =========================================================================
    constexpr int BM = 128;
    constexpr int BN = 256;
    constexpr int KC = 32;
    constexpr int NKT2 = KDIM / KC;
    constexpr int RSB = 80;
    constexpr int SA_BYTES = BM * RSB;
    constexpr int SB_BYTES = BN * RSB;
    constexpr int STAGE = SA_BYTES + SB_BYTES;

    const uint32_t sb = smem_u32(smem_raw);
    const int tid  = threadIdx.x;
    const int wid  = tid >> 5;
    const int lane = tid & 31;

    const int mt = blockIdx.x & 15;
    const int nt = blockIdx.x >> 4;
    const int n0 = nt * BN;

    const int wm = (wid >> 2) * 32;
    const int wn = (wid & 3) * 64;
    const int lr = lane & 15;
    const int lh = (lane >> 4) * 16;

    for (int pass = 0; pass < 2; ++pass) {
        const int m0 = mt * 256 + pass * BM;
        const __nv_bfloat16* gA = reinterpret_cast<const __nv_bfloat16*>(g_Aimg) + (size_t)m0 * KDIM;
        const __nv_bfloat16* gB = reinterpret_cast<const __nv_bfloat16*>(g_Bimg) + (size_t)n0 * KDIM;

        auto fill = [&](int buf, int kt) {
            const uint32_t base = sb + buf * STAGE;
            #pragma unroll
            for (int j = 0; j < 3; ++j) {
                const int q = tid + j * THREADS;
                if (q < 512) {
                    const int r = q >> 2, c = q & 3;
                    cp_async16(base + r * RSB + c * 16, gA + (size_t)r * KDIM + kt * KC + c * 8);
                } else {
                    const int qb = q - 512;
                    const int r = qb >> 2, c = qb & 3;
                    cp_async16(base + SA_BYTES + r * RSB + c * 16,
                               gB + (size_t)r * KDIM + kt * KC + c * 8);
                }
            }
            cp_commit();
        };

        float acc[2][8][4];
        #pragma unroll
        for (int mi = 0; mi < 2; ++mi)
            #pragma unroll
            for (int nf = 0; nf < 8; ++nf)
                #pragma unroll
                for (int k = 0; k < 4; ++k) acc[mi][nf][k] = 0.0f;

        fill(0, 0);

        for (int kt = 0; kt < NKT2; ++kt) {
            if (kt + 1 < NKT2) fill((kt + 1) & 1, kt + 1);
            if (kt + 1 < NKT2) cp_wait<1>(); else cp_wait<0>();
            __syncthreads();

            const uint32_t aB = sb + (kt & 1) * STAGE;
            const uint32_t bB = aB + SA_BYTES;

            #pragma unroll
            for (int s = 0; s < 2; ++s) {
                const int kb = s * 32;
                uint32_t av[2][4];
                #pragma unroll
                for (int mi = 0; mi < 2; ++mi)
                    ldsm_x4(av[mi], aB + (wm + mi * 16 + lr) * RSB + kb + lh);
                uint32_t bv[4][4];
                #pragma unroll
                for (int nb = 0; nb < 4; ++nb)
                    ldsm_x4(bv[nb], bB + (wn + nb * 16 + lr) * RSB + kb + lh);
                #pragma unroll
                for (int mi = 0; mi < 2; ++mi) {
                    #pragma unroll
                    for (int nb = 0; nb < 4; ++nb) {
                        mma16816(acc[mi][nb * 2 + 0], av[mi], bv[nb][0], bv[nb][2]);
                        mma16816(acc[mi][nb * 2 + 1], av[mi], bv[nb][1], bv[nb][3]);
                    }
                }
            }
            __syncthreads();
        }

        const int gr = lane >> 2;
        const int t4 = lane & 3;
        #pragma unroll
        for (int mi = 0; mi < 2; ++mi) {
            const int mrow = m0 + wm + mi * 16 + gr;
            #pragma unroll
            for (int nf = 0; nf < 8; ++nf) {
                const int ncol = n0 + wn + nf * 8 + t4 * 2;
                const float s0 = __ldg(&scale[ncol]);
                const float s1 = __ldg(&scale[ncol + 1]);
                float2 v0 = make_float2(acc[mi][nf][0] * s0, acc[mi][nf][1] * s1);
                float2 v1 = make_float2(acc[mi][nf][2] * s0, acc[mi][nf][3] * s1);
                *reinterpret_cast<float2*>(out + (size_t)mrow * NDIM + ncol) = v0;
                *reinterpret_cast<float2*>(out + (size_t)(mrow + 8) * NDIM + ncol) = v1;
            }
        }
        __syncthreads();
    }
#endif
}

} // namespace s8gemm

extern "C" void kernel_launch(void* const* d_in, const int* in_sizes, int n_in,
                              void* d_out, int out_size)
{
    using namespace s8gemm;

    const void* pa = nullptr;
    const void* pb = nullptr;
    const float* ps = nullptr;
    for (int i = 0; i < n_in; ++i) {
        if (in_sizes[i] == MDIM * KDIM)      pa = d_in[i];
        else if (in_sizes[i] == KDIM * NDIM) pb = d_in[i];
        else if (in_sizes[i] == NDIM)        ps = (const float*)d_in[i];
    }
    if (!pa) pa = d_in[0];
    if (!pb) pb = d_in[1];
    if (!ps) ps = (const float*)d_in[2];
    float* out = (float*)d_out;
    (void)out_size;

    conv_kernel<<<12288, 256>>>(pa, pb);

    cudaFuncSetAttribute(gemm_kernel,
                         cudaFuncAttributeMaxDynamicSharedMemorySize, SMEM_ALLOC);
    gemm_kernel<<<CTAS, THREADS, SMEM_ALLOC>>>(ps, out);
}

// round 12
// speedup vs baseline: 1.3996x; 1.0345x over previous
#include <cuda_runtime.h>
#include <cuda_bf16.h>
#include <cstdint>

#define DEVINL __device__ __forceinline__

#if defined(__CUDA_ARCH__) && \
    (defined(__CUDA_ARCH_FEAT_SM103_ALL) || defined(__CUDA_ARCH_FEAT_SM100_ALL) || \
     defined(__CUDA_ARCH_FEAT_SM101_ALL) || defined(__CUDA_ARCH_SPECIFIC__) || \
     defined(__CUDA_ARCH_FAMILY_SPECIFIC__))
#define HAS_TCGEN05 1
#else
#define HAS_TCGEN05 0
#endif

namespace s8gemm {

constexpr int MDIM = 4096;
constexpr int KDIM = 4096;
constexpr int NDIM = 8192;

// ---- tcgen05 tiling: persistent CTA, 4 tiles of 256(M) x 256(N) each ----
constexpr int NSTAGE = 3;
constexpr int NKT = KDIM / 64;    // 64 k-tiles (64 bf16 = 128B rows)
constexpr int TILES_PER_CTA = 4;

constexpr int A_TILE = 128 * 128;              // 16 KB per 128-row A image block
constexpr int B_TILE = 256 * 128;              // 32 KB per (nt,kt) B image block
constexpr int STAGE_BYTES = 2 * A_TILE + B_TILE;   // 65536
constexpr int OFF_BAR   = NSTAGE * STAGE_BYTES;    // 196608
constexpr int OFF_SCALE = OFF_BAR + 96;
constexpr int SMEM_ALLOC = OFF_SCALE + 256 * 4 + 1024;   // ~198.7 KB

constexpr int TMEM_COLS = 512;    // 2 M-halves x 256 fp32 cols
constexpr int MT = MDIM / 128;    // 32 A image blocks
constexpr int NTL = NDIM / 256;   // 32
constexpr int CTAS = 128;         // 128 CTAs x 4 tiles = 512 tiles, zero waves waste
constexpr int THREADS = 512;

// cg1 kind::f16 idesc: F32 acc, BF16 x BF16, N=128, M=128 (both K-major).
constexpr uint32_t IDESC =
      (1u << 4) | (1u << 7) | (1u << 10)
    | ((128u / 8u) << 17) | ((128u / 16u) << 24);

// K-major SW128 SMEM descriptor (Blackwell version=1): LBO=1, SBO=64.
constexpr uint64_t DESC_BASE_K =
      (uint64_t(2) << 61) | (uint64_t(1) << 46) | (uint64_t(64) << 32) | (uint64_t(1) << 16);

// Scratch images (tcgen05 build):
//   A block (mt128*NKT + kt): 16KB swizzled [128 rows x 128B], mt128 = 0..31.
//   B block (nt*NKT + kt):    32KB swizzled [256 N-rows x 128B].
// Fallback build: linear bf16 A[M][K] / Bt[N][K].
__device__ __align__(1024) uint8_t g_Aimg[(size_t)MT * NKT * A_TILE];    // 32 MB
__device__ __align__(1024) uint8_t g_Bimg[(size_t)NTL * NKT * B_TILE];   // 64 MB

DEVINL uint32_t smem_u32(const void* p) {
    uint32_t a;
    asm("{ .reg .u64 t; cvta.to.shared.u64 t, %1; cvt.u32.u64 %0, t; }" : "=r"(a) : "l"(p));
    return a;
}
DEVINL uint32_t sw128(uint32_t off) { return off ^ ((off >> 3) & 0x70u); }

// ---------------------------------------------------------------------------
// Per-warp dtype classification from the input's first 64 words (L2-broadcast).
// 0=int8-packed, 1=int32-widened, 2=fp32-widened.
// ---------------------------------------------------------------------------
DEVINL int classify_warp(const void* p) {
    const int lane = threadIdx.x & 31;
    const int32_t* w = (const int32_t*)p;
    const float*   f = (const float*)p;
    bool i32ok = true, f32ok = true;
    #pragma unroll
    for (int j = 0; j < 2; ++j) {
        const int idx = lane * 2 + j;
        const int32_t v = w[idx];
        i32ok &= (v >= -128 && v <= 127);
        const float x = f[idx];
        f32ok &= (x >= -128.0f && x <= 128.0f && x == truncf(x));
    }
    const uint32_t bi = __ballot_sync(0xFFFFFFFFu, i32ok);
    const uint32_t bf = __ballot_sync(0xFFFFFFFFu, f32ok);
    return (bi == 0xFFFFFFFFu) ? 1 : ((bf == 0xFFFFFFFFu) ? 2 : 0);
}

// f32->bf16 rn is exact truncation for int8-range integral values -> PRMT.
DEVINL uint32_t pack_bf16x2(float f0, float f1) {
    return __byte_perm(__float_as_uint(f0), __float_as_uint(f1), 0x7632);
}

// Convert 16 logical int8 elems at element index idx into 8 bf16x2 words.
DEVINL void conv16(const void* __restrict__ P, size_t idx, int dt, uint32_t (&u)[8]) {
    if (dt == 1) {
        const uint4* p = reinterpret_cast<const uint4*>((const int32_t*)P + idx);
        #pragma unroll
        for (int q = 0; q < 4; ++q) {
            const uint4 w = p[q];
            u[q * 2 + 0] = pack_bf16x2((float)(int)w.x, (float)(int)w.y);
            u[q * 2 + 1] = pack_bf16x2((float)(int)w.z, (float)(int)w.w);
        }
    } else if (dt == 2) {
        const float4* p = reinterpret_cast<const float4*>((const float*)P + idx);
        #pragma unroll
        for (int q = 0; q < 4; ++q) {
            const float4 w = p[q];
            u[q * 2 + 0] = pack_bf16x2(w.x, w.y);
            u[q * 2 + 1] = pack_bf16x2(w.z, w.w);
        }
    } else {
        const uint4 v = *reinterpret_cast<const uint4*>((const int8_t*)P + idx);
        const int8_t* b = reinterpret_cast<const int8_t*>(&v);
        #pragma unroll
        for (int j = 0; j < 8; ++j)
            u[j] = pack_bf16x2((float)(int)b[2 * j], (float)(int)b[2 * j + 1]);
    }
}

// ---------------------------------------------------------------------------
// Merged pre-pass. Blocks [0,4096): A. Blocks [4096,12288): B transpose.
// ---------------------------------------------------------------------------
__global__ void __launch_bounds__(256) conv_kernel(const void* __restrict__ A,
                                                   const void* __restrict__ B) {
    const int tid = threadIdx.x;
    if (blockIdx.x < 4096) {
        // ------------------------------ A ------------------------------
        const int dt   = classify_warp(A);
        const int w    = tid >> 5;
        const int lane = tid & 31;
        const int task = blockIdx.x * 8 + w;
        const int mg = task >> 6;
        const int kt = task & 63;
        const int m  = mg * 8 + (lane >> 2);
        const int k  = kt * 64 + (lane & 3) * 16;
        uint32_t u[8];
        conv16(A, (size_t)m * KDIM + k, dt, u);
#if HAS_TCGEN05
        const uint32_t mt = (uint32_t)m >> 7, r = (uint32_t)m & 127;
        const uint32_t kl2 = (uint32_t)(lane & 3) * 32;
        uint8_t* blk = g_Aimg + (size_t)(mt * NKT + kt) * A_TILE;
        *reinterpret_cast<uint4*>(blk + sw128(r * 128 + kl2))      = *reinterpret_cast<uint4*>(&u[0]);
        *reinterpret_cast<uint4*>(blk + sw128(r * 128 + kl2 + 16)) = *reinterpret_cast<uint4*>(&u[4]);
#else
        __nv_bfloat16* dst = reinterpret_cast<__nv_bfloat16*>(g_Aimg) + (size_t)m * KDIM + k;
        *reinterpret_cast<uint4*>(dst)     = *reinterpret_cast<uint4*>(&u[0]);
        *reinterpret_cast<uint4*>(dst + 8) = *reinterpret_cast<uint4*>(&u[4]);
#endif
    } else {
        // ------------------------------ B ------------------------------
        __shared__ __nv_bfloat16 t[64][72];
        const int dt = classify_warp(B);
        const int bb = blockIdx.x - 4096;
        const int n0 = (bb & 127) * 64;
        const int k0 = (bb >> 7) * 64;
        const int r  = tid >> 2;
        const int c  = (tid & 3) * 16;

        uint32_t u[8];
        conv16(B, (size_t)(k0 + r) * NDIM + n0 + c, dt, u);
        *reinterpret_cast<uint4*>(&t[r][c])     = *reinterpret_cast<uint4*>(&u[0]);
        *reinterpret_cast<uint4*>(&t[r][c + 8]) = *reinterpret_cast<uint4*>(&u[4]);
        __syncthreads();

        __nv_bfloat16 q[16];
        #pragma unroll
        for (int j = 0; j < 16; ++j) q[j] = t[c + j][r];

#if HAS_TCGEN05
        const uint32_t ng = n0 + r;
        const uint32_t nt = ng >> 8, nl = ng & 255;
        const uint32_t kt = (uint32_t)k0 >> 6;
        uint8_t* blk = g_Bimg + (size_t)(nt * NKT + kt) * B_TILE;
        *reinterpret_cast<uint4*>(blk + sw128(nl * 128 + c * 2))      = *reinterpret_cast<uint4*>(&q[0]);
        *reinterpret_cast<uint4*>(blk + sw128(nl * 128 + c * 2 + 16)) = *reinterpret_cast<uint4*>(&q[8]);
#else
        __nv_bfloat16* dst = reinterpret_cast<__nv_bfloat16*>(g_Bimg) +
                             (size_t)(n0 + r) * KDIM + k0 + c;
        *reinterpret_cast<uint4*>(dst)     = *reinterpret_cast<uint4*>(&q[0]);
        *reinterpret_cast<uint4*>(dst + 8) = *reinterpret_cast<uint4*>(&q[8]);
#endif
    }
}

#if HAS_TCGEN05
DEVINL void mbar_init(uint32_t bar, uint32_t cnt) {
    asm volatile("mbarrier.init.shared.b64 [%0], %1;" :: "r"(bar), "r"(cnt) : "memory");
}
DEVINL void mbar_wait(uint32_t bar, uint32_t parity) {
    asm volatile(
        "{\n\t"
        ".reg .pred P;\n\t"
        "WAIT_%=:\n\t"
        "mbarrier.try_wait.parity.acquire.cta.shared::cta.b64 P, [%0], %1, 0x989680;\n\t"
        "@P bra.uni DONE_%=;\n\t"
        "bra.uni WAIT_%=;\n\t"
        "DONE_%=:\n\t"
        "}" :: "r"(bar), "r"(parity) : "memory");
}
DEVINL void mbar_arrive(uint32_t bar) {
    asm volatile("mbarrier.arrive.shared.b64 _, [%0];" :: "r"(bar) : "memory");
}
DEVINL void mbar_expect_tx(uint32_t bar, uint32_t bytes) {
    asm volatile("mbarrier.arrive.expect_tx.shared.b64 _, [%0], %1;"
                 :: "r"(bar), "r"(bytes) : "memory");
}
DEVINL void bulk_g2s(uint32_t dst, const void* src, uint32_t bytes, uint32_t bar) {
    asm volatile(
        "cp.async.bulk.shared::cluster.global.mbarrier::complete_tx::bytes [%0], [%1], %2, [%3];"
        :: "r"(dst), "l"(src), "r"(bytes), "r"(bar) : "memory");
}
DEVINL void mma_bf16(uint32_t d, uint64_t ad, uint64_t bd, uint32_t idesc, uint32_t acc) {
    asm volatile(
        "{\n\t.reg .pred p;\n\t"
        "setp.ne.u32 p, %5, 0;\n\t"
        "tcgen05.mma.cta_group::1.kind::f16 [%0], %1, %2, %3, {%4, %4, %4, %4}, p;\n\t}"
        :: "r"(d), "l"(ad), "l"(bd), "r"(idesc), "r"(0u), "r"(acc) : "memory");
}
DEVINL void tc_commit(uint32_t bar) {
    asm volatile("tcgen05.commit.cta_group::1.mbarrier::arrive::one.shared::cluster.b64 [%0];"
                 :: "r"(bar) : "memory");
}
DEVINL void tc_fence_after() { asm volatile("tcgen05.fence::after_thread_sync;" ::: "memory"); }
DEVINL void tc_wait_ld() { asm volatile("tcgen05.wait::ld.sync.aligned;" ::: "memory"); }

#define TC_LD_X32(r, addr)                                                     \
    asm volatile(                                                              \
        "tcgen05.ld.sync.aligned.32x32b.x32.b32 "                              \
        "{%0, %1, %2, %3, %4, %5, %6, %7, "                                    \
        " %8, %9, %10, %11, %12, %13, %14, %15, "                              \
        " %16, %17, %18, %19, %20, %21, %22, %23, "                            \
        " %24, %25, %26, %27, %28, %29, %30, %31}, [%32];"                     \
        : "=r"((r)[0]),  "=r"((r)[1]),  "=r"((r)[2]),  "=r"((r)[3]),           \
          "=r"((r)[4]),  "=r"((r)[5]),  "=r"((r)[6]),  "=r"((r)[7]),           \
          "=r"((r)[8]),  "=r"((r)[9]),  "=r"((r)[10]), "=r"((r)[11]),          \
          "=r"((r)[12]), "=r"((r)[13]), "=r"((r)[14]), "=r"((r)[15]),          \
          "=r"((r)[16]), "=r"((r)[17]), "=r"((r)[18]), "=r"((r)[19]),          \
          "=r"((r)[20]), "=r"((r)[21]), "=r"((r)[22]), "=r"((r)[23]),          \
          "=r"((r)[24]), "=r"((r)[25]), "=r"((r)[26]), "=r"((r)[27]),          \
          "=r"((r)[28]), "=r"((r)[29]), "=r"((r)[30]), "=r"((r)[31])           \
        : "r"(addr))
#else
DEVINL void cp_async16(uint32_t dst, const void* src) {
    asm volatile("cp.async.cg.shared.global [%0], [%1], 16;" :: "r"(dst), "l"(src) : "memory");
}
DEVINL void cp_commit() { asm volatile("cp.async.commit_group;" ::: "memory"); }
template <int N> DEVINL void cp_wait() {
    asm volatile("cp.async.wait_group %0;" :: "n"(N) : "memory");
}
DEVINL void ldsm_x4(uint32_t (&r)[4], uint32_t addr) {
    asm volatile("ldmatrix.sync.aligned.m8n8.x4.shared.b16 {%0,%1,%2,%3}, [%4];"
                 : "=r"(r[0]), "=r"(r[1]), "=r"(r[2]), "=r"(r[3]) : "r"(addr));
}
DEVINL void mma16816(float (&d)[4], const uint32_t (&a)[4], uint32_t b0, uint32_t b1) {
    asm volatile(
        "mma.sync.aligned.m16n8k16.row.col.f32.bf16.bf16.f32 "
        "{%0,%1,%2,%3}, {%4,%5,%6,%7}, {%8,%9}, {%0,%1,%2,%3};"
        : "+f"(d[0]), "+f"(d[1]), "+f"(d[2]), "+f"(d[3])
        : "r"(a[0]), "r"(a[1]), "r"(a[2]), "r"(a[3]), "r"(b0), "r"(b1));
}
#endif

__global__ void __launch_bounds__(THREADS, 1)
gemm_kernel(const float* __restrict__ scale, float* __restrict__ out)
{
    extern __shared__ char smem_raw[];

#if HAS_TCGEN05
    // =========================================================================
    // Persistent: CTA c owns nt = c>>2, m-tiles (c&3)*4 .. +3 (same scale,
    // L2 raster preserved). 3-stage ring + TMEM run continuously across
    // tiles; per-tile TMEM handoff via bar_done -> epilogue -> bar_eread.
    // =========================================================================
    const uint32_t sb_raw = smem_u32(smem_raw);
    const uint32_t sb = (sb_raw + 1023u) & ~1023u;
    char* smem = smem_raw + (sb - sb_raw);

    const int tid = threadIdx.x;
    const int wid = tid >> 5;

    const int nt      = blockIdx.x >> 2;
    const int base_mt = (blockIdx.x & 3) * TILES_PER_CTA;   // 256-row tile idx
    const int n0      = nt * 256;

    const uint32_t bar_full0  = sb + OFF_BAR;        // 3 x 8B
    const uint32_t bar_empty0 = sb + OFF_BAR + 24;   // 3 x 8B
    const uint32_t bar_done   = sb + OFF_BAR + 48;   // per-tile MMA completion
    const uint32_t bar_eread  = sb + OFF_BAR + 56;   // per-tile TMEM reads done
    const uint32_t tmem_ptr   = sb + OFF_BAR + 64;
    float* s_scale = reinterpret_cast<float*>(smem + OFF_SCALE);

    if (tid == 0) {
        #pragma unroll
        for (int s = 0; s < NSTAGE; ++s) {
            mbar_init(bar_full0 + s * 8, 1);
            mbar_init(bar_empty0 + s * 8, 1);
        }
        mbar_init(bar_done, 1);    // one tc_commit per tile
        mbar_init(bar_eread, 8);   // 8 epilogue warps arrive per tile
    }
    if (wid == 0) {
        asm volatile("tcgen05.alloc.cta_group::1.sync.aligned.shared::cta.b32 [%0], %1;"
                     :: "r"(tmem_ptr), "r"(TMEM_COLS) : "memory");
    }
    if (tid < 256) s_scale[tid] = scale[n0 + tid];
    __syncthreads();

    uint32_t tmem;
    asm volatile("ld.shared.b32 %0, [%1];" : "=r"(tmem) : "r"(tmem_ptr));

    if (tid == 0) {
        // ---- consumer: per tile wait TMEM free, 64x16 MMAs, commit done ----
        int s = 0, ph = 0;
        for (int i = 0; i < TILES_PER_CTA; ++i) {
            if (i > 0) mbar_wait(bar_eread, (i - 1) & 1);
            for (int kt = 0; kt < NKT; ++kt) {
                mbar_wait(bar_full0 + s * 8, ph);
                const uint32_t stg = sb + (uint32_t)s * STAGE_BYTES;
                #pragma unroll
                for (int mh = 0; mh < 2; ++mh) {
                    const uint64_t adesc = DESC_BASE_K |
                        (((stg + (uint32_t)mh * A_TILE) >> 4) & 0x3FFFu);
                    #pragma unroll
                    for (int nh = 0; nh < 2; ++nh) {
                        const uint64_t bdesc = DESC_BASE_K |
                            (((stg + 2 * A_TILE + (uint32_t)nh * 16384u) >> 4) & 0x3FFFu);
                        const uint32_t dreg = tmem + mh * 256 + nh * 128;
                        #pragma unroll
                        for (int q = 0; q < 4; ++q) {
                            mma_bf16(dreg,
                                     adesc + (uint64_t)(q * 2),
                                     bdesc + (uint64_t)(q * 2),
                                     IDESC,
                                     (kt > 0 || q > 0) ? 1u : 0u);
                        }
                    }
                }
                tc_commit(bar_empty0 + s * 8);
                if (++s == NSTAGE) { s = 0; ph ^= 1; }
            }
            tc_commit(bar_done);
        }
    } else if (tid == 32) {
        // ---- producer: stream 4 tiles x 64 k-tiles through the ring ----
        const uint8_t* gB = g_Bimg + (size_t)(nt * NKT) * B_TILE;
        int s = 0, ph = 1;
        for (int i = 0; i < TILES_PER_CTA; ++i) {
            const int mt = base_mt + i;
            const uint8_t* gA0 = g_Aimg + (size_t)((mt * 2 + 0) * NKT) * A_TILE;
            const uint8_t* gA1 = g_Aimg + (size_t)((mt * 2 + 1) * NKT) * A_TILE;
            for (int kt = 0; kt < NKT; ++kt) {
                mbar_wait(bar_empty0 + s * 8, ph);
                const uint32_t stg  = sb + (uint32_t)s * STAGE_BYTES;
                const uint32_t barf = bar_full0 + s * 8;
                mbar_expect_tx(barf, (uint32_t)STAGE_BYTES);
                bulk_g2s(stg,              gA0 + (size_t)kt * A_TILE, (uint32_t)A_TILE, barf);
                bulk_g2s(stg + A_TILE,     gA1 + (size_t)kt * A_TILE, (uint32_t)A_TILE, barf);
                bulk_g2s(stg + 2 * A_TILE, gB  + (size_t)kt * B_TILE, (uint32_t)B_TILE, barf);
                if (++s == NSTAGE) { s = 0; ph ^= 1; }
            }
        }
    } else if (wid >= 8) {
        // ---- epilogue: 8 warps; warp e: mh = e>>2, sp = wid&3, both cgs ----
        const int lane = tid & 31;
        const int e    = wid - 8;
        const int sp   = wid & 3;          // == e&3; matches TMEM subpartition
        const int mh   = e >> 2;
        for (int i = 0; i < TILES_PER_CTA; ++i) {
            const int m0 = (base_mt + i) * 256;
            const int mrow = m0 + mh * 128 + sp * 32 + lane;
            mbar_wait(bar_done, i & 1);
            tc_fence_after();
            float* orow = out + (size_t)mrow * NDIM + n0;
            #pragma unroll
            for (int cg = 0; cg < 2; ++cg) {
                #pragma unroll
                for (int bp = 0; bp < 2; ++bp) {
                    uint32_t r0[32], r1[32];
                    const uint32_t base = tmem + mh * 256 + cg * 128 + bp * 64;
                    TC_LD_X32(r0, base);
                    TC_LD_X32(r1, base + 32);
                    tc_wait_ld();
                    // unblock the consumer as soon as the LAST read retires
                    if (cg == 1 && bp == 1 && lane == 0) mbar_arrive(bar_eread);
                    const float* sc = s_scale + cg * 128 + bp * 64;
                    float* op = orow + cg * 128 + bp * 64;
                    #pragma unroll
                    for (int j = 0; j < 32; j += 4) {
                        float4 v0, v1;
                        v0.x = __uint_as_float(r0[j+0]) * sc[j+0];
                        v0.y = __uint_as_float(r0[j+1]) * sc[j+1];
                        v0.z = __uint_as_float(r0[j+2]) * sc[j+2];
                        v0.w = __uint_as_float(r0[j+3]) * sc[j+3];
                        v1.x = __uint_as_float(r1[j+0]) * sc[32+j+0];
                        v1.y = __uint_as_float(r1[j+1]) * sc[32+j+1];
                        v1.z = __uint_as_float(r1[j+2]) * sc[32+j+2];
                        v1.w = __uint_as_float(r1[j+3]) * sc[32+j+3];
                        *reinterpret_cast<float4*>(op + j)      = v0;
                        *reinterpret_cast<float4*>(op + 32 + j) = v1;
                    }
                }
            }
        }
    }

    __syncthreads();
    if (wid == 0) {
        asm volatile("tcgen05.dealloc.cta_group::1.sync.aligned.b32 %0, %1;"
                     :: "r"(tmem), "r"(TMEM_COLS));
    }

#else
    // =========================================================================
    // Fallback (compute_103 phase): mma.sync engine, 4 tiles x 2 passes.
    // =========================================================================
    constexpr int BM = 128;
    constexpr int BN = 256;
    constexpr int KC = 32;
    constexpr int NKT2 = KDIM / KC;
    constexpr int RSB = 80;
    constexpr int SA_BYTES = BM * RSB;
    constexpr int SB_BYTES = BN * RSB;
    constexpr int STAGE = SA_BYTES + SB_BYTES;

    const uint32_t sb = smem_u32(smem_raw);
    const int tid  = threadIdx.x;
    const int wid  = tid >> 5;
    const int lane = tid & 31;

    const int nt      = blockIdx.x >> 2;
    const int base_mt = (blockIdx.x & 3) * TILES_PER_CTA;
    const int n0 = nt * BN;

    const int wm = (wid >> 2) * 32;
    const int wn = (wid & 3) * 64;
    const int lr = lane & 15;
    const int lh = (lane >> 4) * 16;

    for (int i = 0; i < TILES_PER_CTA; ++i) {
        for (int pass = 0; pass < 2; ++pass) {
            const int m0 = (base_mt + i) * 256 + pass * BM;
            const __nv_bfloat16* gA = reinterpret_cast<const __nv_bfloat16*>(g_Aimg) + (size_t)m0 * KDIM;
            const __nv_bfloat16* gB = reinterpret_cast<const __nv_bfloat16*>(g_Bimg) + (size_t)n0 * KDIM;

            auto fill = [&](int buf, int kt) {
                const uint32_t base = sb + buf * STAGE;
                #pragma unroll
                for (int j = 0; j < 3; ++j) {
                    const int q = tid + j * THREADS;
                    if (q < 512) {
                        const int r = q >> 2, c = q & 3;
                        cp_async16(base + r * RSB + c * 16, gA + (size_t)r * KDIM + kt * KC + c * 8);
                    } else {
                        const int qb = q - 512;
                        const int r = qb >> 2, c = qb & 3;
                        cp_async16(base + SA_BYTES + r * RSB + c * 16,
                                   gB + (size_t)r * KDIM + kt * KC + c * 8);
                    }
                }
                cp_commit();
            };

            float acc[2][8][4];
            #pragma unroll
            for (int mi = 0; mi < 2; ++mi)
                #pragma unroll
                for (int nf = 0; nf < 8; ++nf)
                    #pragma unroll
                    for (int k = 0; k < 4; ++k) acc[mi][nf][k] = 0.0f;

            fill(0, 0);

            for (int kt = 0; kt < NKT2; ++kt) {
                if (kt + 1 < NKT2) fill((kt + 1) & 1, kt + 1);
                if (kt + 1 < NKT2) cp_wait<1>(); else cp_wait<0>();
                __syncthreads();

                const uint32_t aB = sb + (kt & 1) * STAGE;
                const uint32_t bB = aB + SA_BYTES;

                #pragma unroll
                for (int s = 0; s < 2; ++s) {
                    const int kb = s * 32;
                    uint32_t av[2][4];
                    #pragma unroll
                    for (int mi = 0; mi < 2; ++mi)
                        ldsm_x4(av[mi], aB + (wm + mi * 16 + lr) * RSB + kb + lh);
                    uint32_t bv[4][4];
                    #pragma unroll
                    for (int nb = 0; nb < 4; ++nb)
                        ldsm_x4(bv[nb], bB + (wn + nb * 16 + lr) * RSB + kb + lh);
                    #pragma unroll
                    for (int mi = 0; mi < 2; ++mi) {
                        #pragma unroll
                        for (int nb = 0; nb < 4; ++nb) {
                            mma16816(acc[mi][nb * 2 + 0], av[mi], bv[nb][0], bv[nb][2]);
                            mma16816(acc[mi][nb * 2 + 1], av[mi], bv[nb][1], bv[nb][3]);
                        }
                    }
                }
                __syncthreads();
            }

            const int gr = lane >> 2;
            const int t4 = lane & 3;
            #pragma unroll
            for (int mi = 0; mi < 2; ++mi) {
                const int mrow = m0 + wm + mi * 16 + gr;
                #pragma unroll
                for (int nf = 0; nf < 8; ++nf) {
                    const int ncol = n0 + wn + nf * 8 + t4 * 2;
                    const float s0 = __ldg(&scale[ncol]);
                    const float s1 = __ldg(&scale[ncol + 1]);
                    float2 v0 = make_float2(acc[mi][nf][0] * s0, acc[mi][nf][1] * s1);
                    float2 v1 = make_float2(acc[mi][nf][2] * s0, acc[mi][nf][3] * s1);
                    *reinterpret_cast<float2*>(out + (size_t)mrow * NDIM + ncol) = v0;
                    *reinterpret_cast<float2*>(out + (size_t)(mrow + 8) * NDIM + ncol) = v1;
                }
            }
            __syncthreads();
        }
    }
#endif
}

} // namespace s8gemm

extern "C" void kernel_launch(void* const* d_in, const int* in_sizes, int n_in,
                              void* d_out, int out_size)
{
    using namespace s8gemm;

    const void* pa = nullptr;
    const void* pb = nullptr;
    const float* ps = nullptr;
    for (int i = 0; i < n_in; ++i) {
        if (in_sizes[i] == MDIM * KDIM)      pa = d_in[i];
        else if (in_sizes[i] == KDIM * NDIM) pb = d_in[i];
        else if (in_sizes[i] == NDIM)        ps = (const float*)d_in[i];
    }
    if (!pa) pa = d_in[0];
    if (!pb) pb = d_in[1];
    if (!ps) ps = (const float*)d_in[2];
    float* out = (float*)d_out;
    (void)out_size;

    conv_kernel<<<12288, 256>>>(pa, pb);

    cudaFuncSetAttribute(gemm_kernel,
                         cudaFuncAttributeMaxDynamicSharedMemorySize, SMEM_ALLOC);
    gemm_kernel<<<CTAS, THREADS, SMEM_ALLOC>>>(ps, out);
}